// round 1
// baseline (speedup 1.0000x reference)
#include <cuda_runtime.h>
#include <cstdint>

// ---------------- problem constants ----------------
constexpr int B_   = 2;
constexpr int S_   = 2048;
constexpr int DIM_ = 4096;
constexpr int HQ_  = 32;
constexpr int HKV_ = 8;
constexpr int HD_  = 128;
constexpr int M_   = B_ * S_;          // 4096 rows for all GEMMs

// ---------------- scratch (device globals; no allocation allowed) ----------------
__device__ float g_q_raw[(size_t)M_ * (HQ_ * HD_)];    // 64 MB
__device__ float g_k_raw[(size_t)M_ * (HKV_ * HD_)];   // 16 MB
__device__ float g_v_raw[(size_t)M_ * (HKV_ * HD_)];   // 16 MB
__device__ float g_qt[(size_t)B_ * HQ_ * S_ * HD_];    // 64 MB  (b,h,s,d)
__device__ float g_kt[(size_t)B_ * HKV_ * S_ * HD_];   // 16 MB
__device__ float g_vt[(size_t)B_ * HKV_ * S_ * HD_];   // 16 MB
__device__ float g_attn[(size_t)M_ * (HQ_ * HD_)];     // 64 MB  (b*s, h*d)

// =================================================================
// SGEMM:  C[M,N] = A[M,K] * W[N,K]^T (+ bias[N])
// 128x128 block tile, BK=8, 8x8 per thread, 256 threads.
// =================================================================
constexpr int GBM = 128, GBN = 128, GBK = 8, GTM = 8, GTN = 8;

__global__ __launch_bounds__(256, 2)
void sgemm_tn(const float* __restrict__ A, const float* __restrict__ W,
              const float* __restrict__ bias, float* __restrict__ C,
              int M, int N, int K)
{
    __shared__ float As[GBK][GBM];
    __shared__ float Ws[GBK][GBN];

    const int tid = threadIdx.x;
    const int tcn = tid & 15;        // 16 thread cols
    const int trm = tid >> 4;        // 16 thread rows
    const int ldRow = tid >> 1;      // 0..127
    const int ldK   = (tid & 1) * 4; // 0 or 4

    const float* Ab = A + (size_t)blockIdx.y * GBM * K;
    const float* Wb = W + (size_t)blockIdx.x * GBN * K;

    float acc[GTM][GTN];
#pragma unroll
    for (int i = 0; i < GTM; i++)
#pragma unroll
        for (int j = 0; j < GTN; j++) acc[i][j] = 0.f;

    for (int k0 = 0; k0 < K; k0 += GBK) {
        float4 a4 = *reinterpret_cast<const float4*>(Ab + (size_t)ldRow * K + k0 + ldK);
        float4 w4 = *reinterpret_cast<const float4*>(Wb + (size_t)ldRow * K + k0 + ldK);
        As[ldK + 0][ldRow] = a4.x; As[ldK + 1][ldRow] = a4.y;
        As[ldK + 2][ldRow] = a4.z; As[ldK + 3][ldRow] = a4.w;
        Ws[ldK + 0][ldRow] = w4.x; Ws[ldK + 1][ldRow] = w4.y;
        Ws[ldK + 2][ldRow] = w4.z; Ws[ldK + 3][ldRow] = w4.w;
        __syncthreads();

#pragma unroll
        for (int k = 0; k < GBK; k++) {
            float ra[GTM], rb[GTN];
#pragma unroll
            for (int i = 0; i < GTM; i += 4) {
                float4 t = *reinterpret_cast<const float4*>(&As[k][trm * GTM + i]);
                ra[i] = t.x; ra[i + 1] = t.y; ra[i + 2] = t.z; ra[i + 3] = t.w;
            }
#pragma unroll
            for (int j = 0; j < GTN; j += 4) {
                float4 t = *reinterpret_cast<const float4*>(&Ws[k][tcn * GTN + j]);
                rb[j] = t.x; rb[j + 1] = t.y; rb[j + 2] = t.z; rb[j + 3] = t.w;
            }
#pragma unroll
            for (int i = 0; i < GTM; i++)
#pragma unroll
                for (int j = 0; j < GTN; j++)
                    acc[i][j] = fmaf(ra[i], rb[j], acc[i][j]);
        }
        __syncthreads();
    }

    const int row0 = blockIdx.y * GBM + trm * GTM;
    const int col0 = blockIdx.x * GBN + tcn * GTN;
#pragma unroll
    for (int i = 0; i < GTM; i++) {
#pragma unroll
        for (int j = 0; j < GTN; j += 4) {
            float4 o;
            o.x = acc[i][j + 0]; o.y = acc[i][j + 1];
            o.z = acc[i][j + 2]; o.w = acc[i][j + 3];
            if (bias) {
                o.x += bias[col0 + j + 0]; o.y += bias[col0 + j + 1];
                o.z += bias[col0 + j + 2]; o.w += bias[col0 + j + 3];
            }
            *reinterpret_cast<float4*>(C + (size_t)(row0 + i) * N + col0 + j) = o;
        }
    }
}

// =================================================================
// RoPE + transpose scatter:
//   in  : [B*S, H*HD] (GEMM output)
//   out : [B, H, S, HD]
// rotate_half semantics: out[d]    = x[d]  *cos[d]    - x[d+64]*sin[d]
//                        out[d+64] = x[d+64]*cos[d+64] + x[d]  *sin[d+64]
// =================================================================
__global__ void rope_scatter(const float* __restrict__ in,
                             const float* __restrict__ cosp,
                             const float* __restrict__ sinp,
                             float* __restrict__ out,
                             int H, int doRope)
{
    int idx = blockIdx.x * blockDim.x + threadIdx.x;
    int total = B_ * S_ * H * (HD_ / 2);
    if (idx >= total) return;
    int d = idx & 63;
    int h = (idx >> 6) % H;
    int s = (idx / (64 * H)) % S_;
    int b = idx / (64 * H * S_);

    const float* row = in + (size_t)(b * S_ + s) * ((size_t)H * HD_) + (size_t)h * HD_;
    float x0 = row[d], x1 = row[d + 64];
    float o0, o1;
    if (doRope) {
        float c0 = cosp[s * HD_ + d];
        float c1 = cosp[s * HD_ + d + 64];
        float s0 = sinp[s * HD_ + d];
        float s1 = sinp[s * HD_ + d + 64];
        o0 = x0 * c0 - x1 * s0;
        o1 = x1 * c1 + x0 * s1;
    } else {
        o0 = x0; o1 = x1;
    }
    float* orow = out + ((size_t)(b * H + h) * S_ + s) * HD_;
    orow[d] = o0;
    orow[d + 64] = o1;
}

// =================================================================
// Flash attention, fp32, causal, GQA (4 q heads per kv head).
// Q tile 64 x 128, K tile 64 x 128. Block = 256 threads.
// Q,K stored transposed in smem ([d][row], pad 68) so the score GEMM
// uses contiguous conflict-free LDS.128. Online softmax per row.
// Output written directly to (b*s, h*HD) layout for the O-proj GEMM.
// =================================================================
constexpr int QT = 64, KT = 64;
constexpr int QP = 68;    // padded stride for transposed Q/K  (16B aligned)
constexpr int VP = 132;   // padded stride for V rows          (16B aligned)
constexpr int SP = 65;    // padded stride for score tile

constexpr int FLASH_SMEM_FLOATS = HD_ * QP * 2 + KT * VP + QT * SP + 3 * QT;
constexpr int FLASH_SMEM_BYTES  = FLASH_SMEM_FLOATS * 4;   // 120,832 B

__global__ __launch_bounds__(256, 1)
void flash_attn(const float* __restrict__ Q, const float* __restrict__ Kc,
                const float* __restrict__ Vc, float* __restrict__ Oout)
{
    extern __shared__ float sm[];
    float* Qst  = sm;                    // [HD][QP]
    float* Kst  = Qst + HD_ * QP;        // [HD][QP]
    float* Vs   = Kst + HD_ * QP;        // [KT][VP]
    float* Ps   = Vs + KT * VP;          // [QT][SP]  scores -> probs
    float* mrow = Ps + QT * SP;          // [QT]
    float* lrow = mrow + QT;             // [QT]
    float* frow = lrow + QT;             // [QT]

    const int qt = blockIdx.x;
    const int h  = blockIdx.y;
    const int b  = blockIdx.z;
    const int hk = h >> 2;               // N_REP = 4
    const int tid = threadIdx.x;
    const int tr  = tid >> 4;            // 0..15 (4 rows each)
    const int tc  = tid & 15;            // 0..15 (8 cols each for O, 4 for S)

    const float* Qbase = Q + ((size_t)(b * HQ_ + h) * S_ + (size_t)qt * QT) * HD_;
    const float* Kbase = Kc + (size_t)(b * HKV_ + hk) * S_ * HD_;
    const float* Vbase = Vc + (size_t)(b * HKV_ + hk) * S_ * HD_;

    // --- load Q transposed: lane-per-row mapping -> conflict-free STS ---
    const int lr = tid & 63;             // tile row
    const int lg = tid >> 6;             // 0..3
#pragma unroll
    for (int it = 0; it < 8; it++) {
        int dd = (lg + it * 4) * 4;      // 0..124 step 4, all covered
        float4 v = *reinterpret_cast<const float4*>(Qbase + (size_t)lr * HD_ + dd);
        Qst[(dd + 0) * QP + lr] = v.x;
        Qst[(dd + 1) * QP + lr] = v.y;
        Qst[(dd + 2) * QP + lr] = v.z;
        Qst[(dd + 3) * QP + lr] = v.w;
    }
    if (tid < QT) { mrow[tid] = -1e30f; lrow[tid] = 0.f; }

    float acc[4][8];
#pragma unroll
    for (int i = 0; i < 4; i++)
#pragma unroll
        for (int j = 0; j < 8; j++) acc[i][j] = 0.f;
    __syncthreads();

    const float scale = 0.08838834764831845f;   // 1/sqrt(128)
    const int ntiles = qt + 1;                  // causal: only tiles <= q tile

    for (int j = 0; j < ntiles; j++) {
        const float* Kt = Kbase + (size_t)j * KT * HD_;
        const float* Vt = Vbase + (size_t)j * KT * HD_;

        // K transposed (lane-per-row; L2-served, conflict-free STS)
#pragma unroll
        for (int it = 0; it < 8; it++) {
            int dd = (lg + it * 4) * 4;
            float4 v = *reinterpret_cast<const float4*>(Kt + (size_t)lr * HD_ + dd);
            Kst[(dd + 0) * QP + lr] = v.x;
            Kst[(dd + 1) * QP + lr] = v.y;
            Kst[(dd + 2) * QP + lr] = v.z;
            Kst[(dd + 3) * QP + lr] = v.w;
        }
        // V natural layout (coalesced gmem, STS.128)
#pragma unroll
        for (int it = 0; it < 8; it++) {
            int lin = tid + it * 256;
            int r = lin >> 5;
            int dd = (lin & 31) * 4;
            float4 v = *reinterpret_cast<const float4*>(Vt + (size_t)r * HD_ + dd);
            *reinterpret_cast<float4*>(Vs + r * VP + dd) = v;
        }
        __syncthreads();

        // --- scores: S[r][c] = sum_d Q[r][d] K[c][d], 4x4 per thread ---
        float sc[4][4];
#pragma unroll
        for (int i = 0; i < 4; i++)
#pragma unroll
            for (int c = 0; c < 4; c++) sc[i][c] = 0.f;

#pragma unroll 4
        for (int d = 0; d < HD_; d++) {
            float4 a4 = *reinterpret_cast<const float4*>(Qst + d * QP + tr * 4);
            float4 b4 = *reinterpret_cast<const float4*>(Kst + d * QP + tc * 4);
            float ra[4] = {a4.x, a4.y, a4.z, a4.w};
            float rb[4] = {b4.x, b4.y, b4.z, b4.w};
#pragma unroll
            for (int i = 0; i < 4; i++)
#pragma unroll
                for (int c = 0; c < 4; c++)
                    sc[i][c] = fmaf(ra[i], rb[c], sc[i][c]);
        }

        // mask + scale -> Ps
        const int qglob = qt * QT;
#pragma unroll
        for (int i = 0; i < 4; i++) {
            int r = tr * 4 + i;
#pragma unroll
            for (int c4 = 0; c4 < 4; c4++) {
                int c = tc * 4 + c4;
                float sv = sc[i][c4] * scale;
                if (j * KT + c > qglob + r) sv -= 1e9f;   // matches reference mask add
                Ps[r * SP + c] = sv;
            }
        }
        __syncthreads();

        // --- online softmax: 8 warps x 8 rows each ---
        {
            int warp = tid >> 5, lane = tid & 31;
#pragma unroll
            for (int rr = 0; rr < 8; rr++) {
                int r = warp * 8 + rr;
                float v0 = Ps[r * SP + lane];
                float v1 = Ps[r * SP + lane + 32];
                float mx = fmaxf(v0, v1);
#pragma unroll
                for (int o = 16; o; o >>= 1)
                    mx = fmaxf(mx, __shfl_xor_sync(0xffffffffu, mx, o));
                float mold = mrow[r];
                float mnew = fmaxf(mold, mx);
                float p0 = __expf(v0 - mnew);
                float p1 = __expf(v1 - mnew);
                Ps[r * SP + lane] = p0;
                Ps[r * SP + lane + 32] = p1;
                float psum = p0 + p1;
#pragma unroll
                for (int o = 16; o; o >>= 1)
                    psum += __shfl_xor_sync(0xffffffffu, psum, o);
                if (lane == 0) {
                    float f = __expf(mold - mnew);
                    frow[r] = f;
                    lrow[r] = lrow[r] * f + psum;
                    mrow[r] = mnew;
                }
            }
        }
        __syncthreads();

        // --- rescale accumulators, then O += P * V ---
        float f[4];
#pragma unroll
        for (int i = 0; i < 4; i++) f[i] = frow[tr * 4 + i];
#pragma unroll
        for (int i = 0; i < 4; i++)
#pragma unroll
            for (int jj = 0; jj < 8; jj++) acc[i][jj] *= f[i];

#pragma unroll 2
        for (int c = 0; c < KT; c++) {
            float pa[4];
#pragma unroll
            for (int i = 0; i < 4; i++) pa[i] = Ps[(tr * 4 + i) * SP + c];
            float4 v0 = *reinterpret_cast<const float4*>(Vs + c * VP + tc * 8);
            float4 v1 = *reinterpret_cast<const float4*>(Vs + c * VP + tc * 8 + 4);
            float vb[8] = {v0.x, v0.y, v0.z, v0.w, v1.x, v1.y, v1.z, v1.w};
#pragma unroll
            for (int i = 0; i < 4; i++)
#pragma unroll
                for (int jj = 0; jj < 8; jj++)
                    acc[i][jj] = fmaf(pa[i], vb[jj], acc[i][jj]);
        }
        __syncthreads();
    }

    // --- epilogue: normalize and write (b*s, h*HD) ---
    float inv[4];
#pragma unroll
    for (int i = 0; i < 4; i++) inv[i] = 1.0f / lrow[tr * 4 + i];
#pragma unroll
    for (int i = 0; i < 4; i++) {
        int srow = qt * QT + tr * 4 + i;
        float* orow = Oout + ((size_t)(b * S_ + srow)) * (HQ_ * HD_) + (size_t)h * HD_ + tc * 8;
        float4 o0, o1;
        o0.x = acc[i][0] * inv[i]; o0.y = acc[i][1] * inv[i];
        o0.z = acc[i][2] * inv[i]; o0.w = acc[i][3] * inv[i];
        o1.x = acc[i][4] * inv[i]; o1.y = acc[i][5] * inv[i];
        o1.z = acc[i][6] * inv[i]; o1.w = acc[i][7] * inv[i];
        *reinterpret_cast<float4*>(orow) = o0;
        *reinterpret_cast<float4*>(orow + 4) = o1;
    }
}

// =================================================================
// launch
// =================================================================
extern "C" void kernel_launch(void* const* d_in, const int* in_sizes, int n_in,
                              void* d_out, int out_size)
{
    const float* x    = (const float*)d_in[0];
    const float* cosp = (const float*)d_in[1];
    const float* sinp = (const float*)d_in[2];
    const float* Wq   = (const float*)d_in[3];
    const float* bq   = (const float*)d_in[4];
    const float* Wk   = (const float*)d_in[5];
    const float* bk   = (const float*)d_in[6];
    const float* Wv   = (const float*)d_in[7];
    const float* bv   = (const float*)d_in[8];
    const float* Wo   = (const float*)d_in[9];
    float* out = (float*)d_out;

    float *q_raw, *k_raw, *v_raw, *qt, *kt, *vt, *attn;
    cudaGetSymbolAddress((void**)&q_raw, g_q_raw);
    cudaGetSymbolAddress((void**)&k_raw, g_k_raw);
    cudaGetSymbolAddress((void**)&v_raw, g_v_raw);
    cudaGetSymbolAddress((void**)&qt,    g_qt);
    cudaGetSymbolAddress((void**)&kt,    g_kt);
    cudaGetSymbolAddress((void**)&vt,    g_vt);
    cudaGetSymbolAddress((void**)&attn,  g_attn);

    cudaFuncSetAttribute(flash_attn, cudaFuncAttributeMaxDynamicSharedMemorySize,
                         FLASH_SMEM_BYTES);

    dim3 blk(256);

    // QKV projections
    sgemm_tn<<<dim3((HQ_ * HD_) / GBN, M_ / GBM), blk>>>(x, Wq, bq, q_raw, M_, HQ_ * HD_, DIM_);
    sgemm_tn<<<dim3((HKV_ * HD_) / GBN, M_ / GBM), blk>>>(x, Wk, bk, k_raw, M_, HKV_ * HD_, DIM_);
    sgemm_tn<<<dim3((HKV_ * HD_) / GBN, M_ / GBM), blk>>>(x, Wv, bv, v_raw, M_, HKV_ * HD_, DIM_);

    // RoPE + transpose to (b,h,s,d)
    {
        int npq = B_ * S_ * HQ_ * (HD_ / 2);
        rope_scatter<<<(npq + 255) / 256, 256>>>(q_raw, cosp, sinp, qt, HQ_, 1);
        int npk = B_ * S_ * HKV_ * (HD_ / 2);
        rope_scatter<<<(npk + 255) / 256, 256>>>(k_raw, cosp, sinp, kt, HKV_, 1);
        rope_scatter<<<(npk + 255) / 256, 256>>>(v_raw, cosp, sinp, vt, HKV_, 0);
    }

    // causal GQA flash attention -> (b*s, h*HD)
    flash_attn<<<dim3(S_ / QT, HQ_, B_), blk, FLASH_SMEM_BYTES>>>(qt, kt, vt, attn);

    // output projection
    sgemm_tn<<<dim3(DIM_ / GBN, M_ / GBM), blk>>>(attn, Wo, nullptr, out, M_, DIM_, HQ_ * HD_);
}

// round 4
// speedup vs baseline: 1.6448x; 1.6448x over previous
#include <cuda_runtime.h>
#include <cuda_bf16.h>
#include <cstdint>

// ---------------- problem constants ----------------
constexpr int B_   = 2;
constexpr int S_   = 2048;
constexpr int DIM_ = 4096;
constexpr int HQ_  = 32;
constexpr int HKV_ = 8;
constexpr int HD_  = 128;
constexpr int M_   = B_ * S_;          // 4096 rows for all GEMMs
constexpr int K0_  = 4096;             // inner dim of every GEMM here
constexpr int KP_  = 3 * K0_;          // split-bf16 tripled K = 12288

// ---------------- scratch (device globals; no allocation allowed) ----------------
__device__ float g_q_raw[(size_t)M_ * (HQ_ * HD_)];
__device__ float g_k_raw[(size_t)M_ * (HKV_ * HD_)];
__device__ float g_v_raw[(size_t)M_ * (HKV_ * HD_)];
__device__ float g_qt[(size_t)B_ * HQ_ * S_ * HD_];
__device__ float g_kt[(size_t)B_ * HKV_ * S_ * HD_];
__device__ float g_vt[(size_t)B_ * HKV_ * S_ * HD_];
__device__ float g_attn[(size_t)M_ * (HQ_ * HD_)];

// split-bf16 operands (block layout: [rows, 3K], blocks of K cols)
__device__ __nv_bfloat16 g_x3[(size_t)M_ * KP_];
__device__ __nv_bfloat16 g_wq3[(size_t)(HQ_ * HD_) * KP_];
__device__ __nv_bfloat16 g_wk3[(size_t)(HKV_ * HD_) * KP_];
__device__ __nv_bfloat16 g_wv3[(size_t)(HKV_ * HD_) * KP_];
__device__ __nv_bfloat16 g_wo3[(size_t)DIM_ * KP_];
__device__ __nv_bfloat16 g_attn3[(size_t)M_ * KP_];

// =================================================================
// base-ISA tensor helpers (sm_80-level PTX: HMMA / ldmatrix / cp.async)
// =================================================================
__device__ __forceinline__ uint32_t smem_u32(const void* p) {
    uint32_t a;
    asm("{ .reg .u64 t; cvta.to.shared.u64 t, %1; cvt.u32.u64 %0, t; }" : "=r"(a) : "l"(p));
    return a;
}
__device__ __forceinline__ void cp_async16(uint32_t dst, const void* src) {
    asm volatile("cp.async.cg.shared.global [%0], [%1], 16;" :: "r"(dst), "l"(src));
}
__device__ __forceinline__ void cp_commit() {
    asm volatile("cp.async.commit_group;");
}
template <int N>
__device__ __forceinline__ void cp_wait() {
    asm volatile("cp.async.wait_group %0;" :: "n"(N));
}
__device__ __forceinline__ void ldmatrix_x4(uint32_t& r0, uint32_t& r1,
                                            uint32_t& r2, uint32_t& r3, uint32_t addr) {
    asm volatile("ldmatrix.sync.aligned.m8n8.x4.shared.b16 {%0,%1,%2,%3}, [%4];"
                 : "=r"(r0), "=r"(r1), "=r"(r2), "=r"(r3) : "r"(addr));
}
__device__ __forceinline__ void mma_bf16(float& c0, float& c1, float& c2, float& c3,
                                         uint32_t a0, uint32_t a1, uint32_t a2, uint32_t a3,
                                         uint32_t b0, uint32_t b1) {
    asm volatile(
        "mma.sync.aligned.m16n8k16.row.col.f32.bf16.bf16.f32 "
        "{%0,%1,%2,%3}, {%4,%5,%6,%7}, {%8,%9}, {%0,%1,%2,%3};"
        : "+f"(c0), "+f"(c1), "+f"(c2), "+f"(c3)
        : "r"(a0), "r"(a1), "r"(a2), "r"(a3), "r"(b0), "r"(b1));
}

// =================================================================
// split-bf16 conversion: in [rows, K0] fp32 -> out [rows, 3*K0] bf16
//   A-side: loBlock=2  -> [hi | hi | lo]
//   B-side: loBlock=1  -> [hi | lo | hi]
// =================================================================
__global__ void split3(const float* __restrict__ in, __nv_bfloat16* __restrict__ out,
                       int rows, int loBlock)
{
    int idx = blockIdx.x * blockDim.x + threadIdx.x;
    int perRow = K0_ / 4;
    int total = rows * perRow;
    if (idx >= total) return;
    int r = idx / perRow;
    int k4 = (idx - r * perRow) * 4;
    float4 v = *reinterpret_cast<const float4*>(in + (size_t)r * K0_ + k4);
    float vv[4] = {v.x, v.y, v.z, v.w};
    __nv_bfloat16 hi[4], lo[4];
#pragma unroll
    for (int i = 0; i < 4; i++) {
        hi[i] = __float2bfloat16(vv[i]);
        lo[i] = __float2bfloat16(vv[i] - __bfloat162float(hi[i]));
    }
    __nv_bfloat16* o = out + (size_t)r * KP_;
    __nv_bfloat162 hp0 = __nv_bfloat162(hi[0], hi[1]);
    __nv_bfloat162 hp1 = __nv_bfloat162(hi[2], hi[3]);
    __nv_bfloat162 lp0 = __nv_bfloat162(lo[0], lo[1]);
    __nv_bfloat162 lp1 = __nv_bfloat162(lo[2], lo[3]);
#pragma unroll
    for (int b = 0; b < 3; b++) {
        __nv_bfloat162* dst = reinterpret_cast<__nv_bfloat162*>(o + b * K0_ + k4);
        if (b == loBlock) { dst[0] = lp0; dst[1] = lp1; }
        else              { dst[0] = hp0; dst[1] = hp1; }
    }
}

// =================================================================
// HMMA bf16 GEMM:  C[M,N] = A3[M,KP] * W3[N,KP]^T (+bias), fp32 out
// 128x128x32 tile, 256 threads, warp grid 4(m) x 2(n), warp tile 32x64.
// m16n8k16 fragments via ldmatrix; cp.async double-buffered smem.
// =================================================================
constexpr int BKt  = 32;                 // bf16 k per tile
constexpr int ASTR = 40;                 // row stride in bf16 (80B: conflict-free ldmatrix)
constexpr int TILE_E = 128 * ASTR;       // elems per buffer

__global__ __launch_bounds__(256, 2)
void gemm_hmma(const __nv_bfloat16* __restrict__ A, const __nv_bfloat16* __restrict__ W,
               const float* __restrict__ bias, float* __restrict__ C, int N)
{
    __shared__ __nv_bfloat16 As[2][TILE_E];
    __shared__ __nv_bfloat16 Ws[2][TILE_E];

    const int tid  = threadIdx.x;
    const int wid  = tid >> 5;
    const int lane = tid & 31;
    const int wm   = wid & 3;            // 0..3  (m)
    const int wn   = wid >> 2;           // 0..1  (n)

    const int nb = blockIdx.x, mb = blockIdx.y;
    const __nv_bfloat16* Abase = A + (size_t)mb * 128 * KP_;
    const __nv_bfloat16* Wbase = W + (size_t)nb * 128 * KP_;

    const uint32_t asm0 = smem_u32(As[0]);
    const uint32_t asm1 = smem_u32(As[1]);
    const uint32_t wsm0 = smem_u32(Ws[0]);
    const uint32_t wsm1 = smem_u32(Ws[1]);

    // per-thread load slots: lin = tid*2 + i; seg(16B) = lin&3, row = lin>>2
    const int l0 = tid * 2, l1 = tid * 2 + 1;
    const int r0 = l0 >> 2, s0 = l0 & 3;
    const int r1 = l1 >> 2, s1 = l1 & 3;

    auto load_tile = [&](int c, int buf) {
        uint32_t ad = (buf ? asm1 : asm0);
        uint32_t wd = (buf ? wsm1 : wsm0);
        const char* Ak = reinterpret_cast<const char*>(Abase + (size_t)c * BKt);
        const char* Wk = reinterpret_cast<const char*>(Wbase + (size_t)c * BKt);
        cp_async16(ad + (uint32_t)(r0 * ASTR * 2 + s0 * 16), Ak + (size_t)r0 * KP_ * 2 + s0 * 16);
        cp_async16(ad + (uint32_t)(r1 * ASTR * 2 + s1 * 16), Ak + (size_t)r1 * KP_ * 2 + s1 * 16);
        cp_async16(wd + (uint32_t)(r0 * ASTR * 2 + s0 * 16), Wk + (size_t)r0 * KP_ * 2 + s0 * 16);
        cp_async16(wd + (uint32_t)(r1 * ASTR * 2 + s1 * 16), Wk + (size_t)r1 * KP_ * 2 + s1 * 16);
    };

    // ldmatrix per-lane byte offsets (relative to buffer base, before ks shift)
    // A x4 (per mi): rows wm*32+mi*16+(lane&15), col half (lane>>4)*8
    const uint32_t aoffs = (uint32_t)(((wm * 32 + (lane & 15)) * ASTR + (lane >> 4) * 8) * 2);
    // B x4 (per p): rows wn*64 + (2p + (g>>1))*8 + (lane&7), col (g&1)*8,  g = lane>>3
    const int g = lane >> 3;
    const uint32_t boffs = (uint32_t)(((wn * 64 + ((g >> 1) * 8) + (lane & 7)) * ASTR + (g & 1) * 8) * 2);

    float acc[2][8][4];
#pragma unroll
    for (int mi = 0; mi < 2; mi++)
#pragma unroll
        for (int ni = 0; ni < 8; ni++)
#pragma unroll
            for (int q = 0; q < 4; q++) acc[mi][ni][q] = 0.f;

    const int NT = KP_ / BKt;            // 384
    load_tile(0, 0);
    cp_commit();

    for (int c = 0; c < NT; c++) {
        const int buf = c & 1;
        if (c + 1 < NT) { load_tile(c + 1, (c + 1) & 1); cp_commit(); cp_wait<1>(); }
        else            { cp_wait<0>(); }
        __syncthreads();

        const uint32_t ab = (buf ? asm1 : asm0);
        const uint32_t wb = (buf ? wsm1 : wsm0);
#pragma unroll
        for (int ks = 0; ks < 2; ks++) {
            const uint32_t kshift = (uint32_t)(ks * 16 * 2);
            uint32_t a[2][4];
#pragma unroll
            for (int mi = 0; mi < 2; mi++)
                ldmatrix_x4(a[mi][0], a[mi][1], a[mi][2], a[mi][3],
                            ab + aoffs + (uint32_t)(mi * 16 * ASTR * 2) + kshift);
            uint32_t bfr[8][2];
#pragma unroll
            for (int p = 0; p < 4; p++) {
                uint32_t t0, t1, t2, t3;
                ldmatrix_x4(t0, t1, t2, t3,
                            wb + boffs + (uint32_t)(p * 16 * ASTR * 2) + kshift);
                bfr[2 * p + 0][0] = t0; bfr[2 * p + 0][1] = t1;
                bfr[2 * p + 1][0] = t2; bfr[2 * p + 1][1] = t3;
            }
#pragma unroll
            for (int mi = 0; mi < 2; mi++)
#pragma unroll
                for (int ni = 0; ni < 8; ni++)
                    mma_bf16(acc[mi][ni][0], acc[mi][ni][1], acc[mi][ni][2], acc[mi][ni][3],
                             a[mi][0], a[mi][1], a[mi][2], a[mi][3],
                             bfr[ni][0], bfr[ni][1]);
        }
        __syncthreads();
    }

    // epilogue: c0,c1 -> (row, col..col+1); c2,c3 -> (row+8, col..col+1)
    const int mrow0 = mb * 128 + wm * 32 + (lane >> 2);
    const int ncol0 = nb * 128 + wn * 64 + (lane & 3) * 2;
#pragma unroll
    for (int mi = 0; mi < 2; mi++) {
#pragma unroll
        for (int ni = 0; ni < 8; ni++) {
            int row = mrow0 + mi * 16;
            int col = ncol0 + ni * 8;
            float b0 = 0.f, b1 = 0.f;
            if (bias) { b0 = bias[col]; b1 = bias[col + 1]; }
            float2 v0 = {acc[mi][ni][0] + b0, acc[mi][ni][1] + b1};
            float2 v1 = {acc[mi][ni][2] + b0, acc[mi][ni][3] + b1};
            *reinterpret_cast<float2*>(C + (size_t)row * N + col) = v0;
            *reinterpret_cast<float2*>(C + (size_t)(row + 8) * N + col) = v1;
        }
    }
}

// =================================================================
// RoPE + transpose scatter (unchanged)
// =================================================================
__global__ void rope_scatter(const float* __restrict__ in,
                             const float* __restrict__ cosp,
                             const float* __restrict__ sinp,
                             float* __restrict__ out,
                             int H, int doRope)
{
    int idx = blockIdx.x * blockDim.x + threadIdx.x;
    int total = B_ * S_ * H * (HD_ / 2);
    if (idx >= total) return;
    int d = idx & 63;
    int h = (idx >> 6) % H;
    int s = (idx / (64 * H)) % S_;
    int b = idx / (64 * H * S_);

    const float* row = in + (size_t)(b * S_ + s) * ((size_t)H * HD_) + (size_t)h * HD_;
    float x0 = row[d], x1 = row[d + 64];
    float o0, o1;
    if (doRope) {
        float c0 = cosp[s * HD_ + d];
        float c1 = cosp[s * HD_ + d + 64];
        float s0 = sinp[s * HD_ + d];
        float s1 = sinp[s * HD_ + d + 64];
        o0 = x0 * c0 - x1 * s0;
        o1 = x1 * c1 + x0 * s1;
    } else {
        o0 = x0; o1 = x1;
    }
    float* orow = out + ((size_t)(b * H + h) * S_ + s) * HD_;
    orow[d] = o0;
    orow[d + 64] = o1;
}

// =================================================================
// Flash attention (fp32, unchanged — proven correct in R1)
// =================================================================
constexpr int QT = 64, KT = 64;
constexpr int QP = 68;
constexpr int VP = 132;
constexpr int SP = 65;
constexpr int FLASH_SMEM_FLOATS = HD_ * QP * 2 + KT * VP + QT * SP + 3 * QT;
constexpr int FLASH_SMEM_BYTES  = FLASH_SMEM_FLOATS * 4;

__global__ __launch_bounds__(256, 1)
void flash_attn(const float* __restrict__ Q, const float* __restrict__ Kc,
                const float* __restrict__ Vc, float* __restrict__ Oout)
{
    extern __shared__ float sm[];
    float* Qst  = sm;
    float* Kst  = Qst + HD_ * QP;
    float* Vs   = Kst + HD_ * QP;
    float* Ps   = Vs + KT * VP;
    float* mrow = Ps + QT * SP;
    float* lrow = mrow + QT;
    float* frow = lrow + QT;

    const int qt = blockIdx.x;
    const int h  = blockIdx.y;
    const int b  = blockIdx.z;
    const int hk = h >> 2;
    const int tid = threadIdx.x;
    const int tr  = tid >> 4;
    const int tc  = tid & 15;

    const float* Qbase = Q + ((size_t)(b * HQ_ + h) * S_ + (size_t)qt * QT) * HD_;
    const float* Kbase = Kc + (size_t)(b * HKV_ + hk) * S_ * HD_;
    const float* Vbase = Vc + (size_t)(b * HKV_ + hk) * S_ * HD_;

    const int lr = tid & 63;
    const int lg = tid >> 6;
#pragma unroll
    for (int it = 0; it < 8; it++) {
        int dd = (lg + it * 4) * 4;
        float4 v = *reinterpret_cast<const float4*>(Qbase + (size_t)lr * HD_ + dd);
        Qst[(dd + 0) * QP + lr] = v.x;
        Qst[(dd + 1) * QP + lr] = v.y;
        Qst[(dd + 2) * QP + lr] = v.z;
        Qst[(dd + 3) * QP + lr] = v.w;
    }
    if (tid < QT) { mrow[tid] = -1e30f; lrow[tid] = 0.f; }

    float acc[4][8];
#pragma unroll
    for (int i = 0; i < 4; i++)
#pragma unroll
        for (int j = 0; j < 8; j++) acc[i][j] = 0.f;
    __syncthreads();

    const float scale = 0.08838834764831845f;
    const int ntiles = qt + 1;

    for (int j = 0; j < ntiles; j++) {
        const float* Kt = Kbase + (size_t)j * KT * HD_;
        const float* Vt = Vbase + (size_t)j * KT * HD_;
#pragma unroll
        for (int it = 0; it < 8; it++) {
            int dd = (lg + it * 4) * 4;
            float4 v = *reinterpret_cast<const float4*>(Kt + (size_t)lr * HD_ + dd);
            Kst[(dd + 0) * QP + lr] = v.x;
            Kst[(dd + 1) * QP + lr] = v.y;
            Kst[(dd + 2) * QP + lr] = v.z;
            Kst[(dd + 3) * QP + lr] = v.w;
        }
#pragma unroll
        for (int it = 0; it < 8; it++) {
            int lin = tid + it * 256;
            int r = lin >> 5;
            int dd = (lin & 31) * 4;
            float4 v = *reinterpret_cast<const float4*>(Vt + (size_t)r * HD_ + dd);
            *reinterpret_cast<float4*>(Vs + r * VP + dd) = v;
        }
        __syncthreads();

        float sc[4][4];
#pragma unroll
        for (int i = 0; i < 4; i++)
#pragma unroll
            for (int c = 0; c < 4; c++) sc[i][c] = 0.f;

#pragma unroll 4
        for (int d = 0; d < HD_; d++) {
            float4 a4 = *reinterpret_cast<const float4*>(Qst + d * QP + tr * 4);
            float4 b4 = *reinterpret_cast<const float4*>(Kst + d * QP + tc * 4);
            float ra[4] = {a4.x, a4.y, a4.z, a4.w};
            float rb[4] = {b4.x, b4.y, b4.z, b4.w};
#pragma unroll
            for (int i = 0; i < 4; i++)
#pragma unroll
                for (int c = 0; c < 4; c++)
                    sc[i][c] = fmaf(ra[i], rb[c], sc[i][c]);
        }

        const int qglob = qt * QT;
#pragma unroll
        for (int i = 0; i < 4; i++) {
            int r = tr * 4 + i;
#pragma unroll
            for (int c4 = 0; c4 < 4; c4++) {
                int c = tc * 4 + c4;
                float sv = sc[i][c4] * scale;
                if (j * KT + c > qglob + r) sv -= 1e9f;
                Ps[r * SP + c] = sv;
            }
        }
        __syncthreads();

        {
            int warp = tid >> 5, lane = tid & 31;
#pragma unroll
            for (int rr = 0; rr < 8; rr++) {
                int r = warp * 8 + rr;
                float v0 = Ps[r * SP + lane];
                float v1 = Ps[r * SP + lane + 32];
                float mx = fmaxf(v0, v1);
#pragma unroll
                for (int o = 16; o; o >>= 1)
                    mx = fmaxf(mx, __shfl_xor_sync(0xffffffffu, mx, o));
                float mold = mrow[r];
                float mnew = fmaxf(mold, mx);
                float p0 = __expf(v0 - mnew);
                float p1 = __expf(v1 - mnew);
                Ps[r * SP + lane] = p0;
                Ps[r * SP + lane + 32] = p1;
                float psum = p0 + p1;
#pragma unroll
                for (int o = 16; o; o >>= 1)
                    psum += __shfl_xor_sync(0xffffffffu, psum, o);
                if (lane == 0) {
                    float f = __expf(mold - mnew);
                    frow[r] = f;
                    lrow[r] = lrow[r] * f + psum;
                    mrow[r] = mnew;
                }
            }
        }
        __syncthreads();

        float f[4];
#pragma unroll
        for (int i = 0; i < 4; i++) f[i] = frow[tr * 4 + i];
#pragma unroll
        for (int i = 0; i < 4; i++)
#pragma unroll
            for (int jj = 0; jj < 8; jj++) acc[i][jj] *= f[i];

#pragma unroll 2
        for (int c = 0; c < KT; c++) {
            float pa[4];
#pragma unroll
            for (int i = 0; i < 4; i++) pa[i] = Ps[(tr * 4 + i) * SP + c];
            float4 v0 = *reinterpret_cast<const float4*>(Vs + c * VP + tc * 8);
            float4 v1 = *reinterpret_cast<const float4*>(Vs + c * VP + tc * 8 + 4);
            float vb[8] = {v0.x, v0.y, v0.z, v0.w, v1.x, v1.y, v1.z, v1.w};
#pragma unroll
            for (int i = 0; i < 4; i++)
#pragma unroll
                for (int jj = 0; jj < 8; jj++)
                    acc[i][jj] = fmaf(pa[i], vb[jj], acc[i][jj]);
        }
        __syncthreads();
    }

    float inv[4];
#pragma unroll
    for (int i = 0; i < 4; i++) inv[i] = 1.0f / lrow[tr * 4 + i];
#pragma unroll
    for (int i = 0; i < 4; i++) {
        int srow = qt * QT + tr * 4 + i;
        float* orow = Oout + ((size_t)(b * S_ + srow)) * (HQ_ * HD_) + (size_t)h * HD_ + tc * 8;
        float4 o0, o1;
        o0.x = acc[i][0] * inv[i]; o0.y = acc[i][1] * inv[i];
        o0.z = acc[i][2] * inv[i]; o0.w = acc[i][3] * inv[i];
        o1.x = acc[i][4] * inv[i]; o1.y = acc[i][5] * inv[i];
        o1.z = acc[i][6] * inv[i]; o1.w = acc[i][7] * inv[i];
        *reinterpret_cast<float4*>(orow) = o0;
        *reinterpret_cast<float4*>(orow + 4) = o1;
    }
}

// =================================================================
// launch
// =================================================================
extern "C" void kernel_launch(void* const* d_in, const int* in_sizes, int n_in,
                              void* d_out, int out_size)
{
    const float* x    = (const float*)d_in[0];
    const float* cosp = (const float*)d_in[1];
    const float* sinp = (const float*)d_in[2];
    const float* Wq   = (const float*)d_in[3];
    const float* bq   = (const float*)d_in[4];
    const float* Wk   = (const float*)d_in[5];
    const float* bk   = (const float*)d_in[6];
    const float* Wv   = (const float*)d_in[7];
    const float* bv   = (const float*)d_in[8];
    const float* Wo   = (const float*)d_in[9];
    float* out = (float*)d_out;

    float *q_raw, *k_raw, *v_raw, *qt, *kt, *vt, *attn;
    __nv_bfloat16 *x3, *wq3, *wk3, *wv3, *wo3, *attn3;
    cudaGetSymbolAddress((void**)&q_raw, g_q_raw);
    cudaGetSymbolAddress((void**)&k_raw, g_k_raw);
    cudaGetSymbolAddress((void**)&v_raw, g_v_raw);
    cudaGetSymbolAddress((void**)&qt,    g_qt);
    cudaGetSymbolAddress((void**)&kt,    g_kt);
    cudaGetSymbolAddress((void**)&vt,    g_vt);
    cudaGetSymbolAddress((void**)&attn,  g_attn);
    cudaGetSymbolAddress((void**)&x3,    g_x3);
    cudaGetSymbolAddress((void**)&wq3,   g_wq3);
    cudaGetSymbolAddress((void**)&wk3,   g_wk3);
    cudaGetSymbolAddress((void**)&wv3,   g_wv3);
    cudaGetSymbolAddress((void**)&wo3,   g_wo3);
    cudaGetSymbolAddress((void**)&attn3, g_attn3);

    cudaFuncSetAttribute(flash_attn, cudaFuncAttributeMaxDynamicSharedMemorySize,
                         FLASH_SMEM_BYTES);

    // split fp32 -> (hi|hi|lo) / (hi|lo|hi) bf16 operands
    auto splits = [&](const float* src, __nv_bfloat16* dst, int rows, int loB) {
        int total = rows * (K0_ / 4);
        split3<<<(total + 255) / 256, 256>>>(src, dst, rows, loB);
    };
    splits(x,  x3,  M_,         2);
    splits(Wq, wq3, HQ_ * HD_,  1);
    splits(Wk, wk3, HKV_ * HD_, 1);
    splits(Wv, wv3, HKV_ * HD_, 1);
    splits(Wo, wo3, DIM_,       1);

    // QKV projections on HMMA tensor cores
    gemm_hmma<<<dim3((HQ_ * HD_) / 128, M_ / 128), 256>>>(x3, wq3, bq, q_raw, HQ_ * HD_);
    gemm_hmma<<<dim3((HKV_ * HD_) / 128, M_ / 128), 256>>>(x3, wk3, bk, k_raw, HKV_ * HD_);
    gemm_hmma<<<dim3((HKV_ * HD_) / 128, M_ / 128), 256>>>(x3, wv3, bv, v_raw, HKV_ * HD_);

    // RoPE + transpose to (b,h,s,d)
    {
        int npq = B_ * S_ * HQ_ * (HD_ / 2);
        rope_scatter<<<(npq + 255) / 256, 256>>>(q_raw, cosp, sinp, qt, HQ_, 1);
        int npk = B_ * S_ * HKV_ * (HD_ / 2);
        rope_scatter<<<(npk + 255) / 256, 256>>>(k_raw, cosp, sinp, kt, HKV_, 1);
        rope_scatter<<<(npk + 255) / 256, 256>>>(v_raw, cosp, sinp, vt, HKV_, 0);
    }

    // causal GQA flash attention -> (b*s, h*HD)
    flash_attn<<<dim3(S_ / QT, HQ_, B_), 256, FLASH_SMEM_BYTES>>>(qt, kt, vt, attn);

    // output projection on HMMA
    splits(attn, attn3, M_, 2);
    gemm_hmma<<<dim3(DIM_ / 128, M_ / 128), 256>>>(attn3, wo3, nullptr, out, DIM_);
}

// round 6
// speedup vs baseline: 1.9102x; 1.1614x over previous
#include <cuda_runtime.h>
#include <cuda_bf16.h>
#include <cstdint>

// ---------------- problem constants ----------------
constexpr int B_   = 2;
constexpr int S_   = 2048;
constexpr int DIM_ = 4096;
constexpr int HQ_  = 32;
constexpr int HKV_ = 8;
constexpr int HD_  = 128;
constexpr int M_   = B_ * S_;          // 4096 rows for all GEMMs
constexpr int K0_  = 4096;             // inner dim of every GEMM here
constexpr int KP_  = 3 * K0_;          // split-bf16 tripled K = 12288
constexpr int NQKV = HQ_ * HD_ + 2 * HKV_ * HD_;   // 6144 fused QKV cols

// ---------------- scratch (device globals; no allocation allowed) ----------------
__device__ float g_qkv_raw[(size_t)M_ * NQKV];        // fused QKV GEMM output
__device__ float g_qt[(size_t)B_ * HQ_ * S_ * HD_];
__device__ float g_kt[(size_t)B_ * HKV_ * S_ * HD_];
__device__ float g_vt[(size_t)B_ * HKV_ * S_ * HD_];
__device__ float g_attn[(size_t)M_ * (HQ_ * HD_)];
__device__ float g_bqkv[NQKV];

// split-bf16 operands (block layout: [rows, 3K], blocks of K cols)
__device__ __nv_bfloat16 g_x3[(size_t)M_ * KP_];
__device__ __nv_bfloat16 g_wqkv3[(size_t)NQKV * KP_];   // Wq|Wk|Wv rows
__device__ __nv_bfloat16 g_wo3[(size_t)DIM_ * KP_];
__device__ __nv_bfloat16 g_attn3[(size_t)M_ * KP_];

// =================================================================
// base-ISA tensor helpers (sm_80-level PTX: HMMA / ldmatrix / cp.async)
// =================================================================
__device__ __forceinline__ uint32_t smem_u32(const void* p) {
    uint32_t a;
    asm("{ .reg .u64 t; cvta.to.shared.u64 t, %1; cvt.u32.u64 %0, t; }" : "=r"(a) : "l"(p));
    return a;
}
__device__ __forceinline__ void cp_async16(uint32_t dst, const void* src) {
    asm volatile("cp.async.cg.shared.global [%0], [%1], 16;" :: "r"(dst), "l"(src));
}
__device__ __forceinline__ void cp_commit() {
    asm volatile("cp.async.commit_group;");
}
template <int N>
__device__ __forceinline__ void cp_wait() {
    asm volatile("cp.async.wait_group %0;" :: "n"(N));
}
__device__ __forceinline__ void ldmatrix_x4(uint32_t& r0, uint32_t& r1,
                                            uint32_t& r2, uint32_t& r3, uint32_t addr) {
    asm volatile("ldmatrix.sync.aligned.m8n8.x4.shared.b16 {%0,%1,%2,%3}, [%4];"
                 : "=r"(r0), "=r"(r1), "=r"(r2), "=r"(r3) : "r"(addr));
}
__device__ __forceinline__ void mma_bf16(float& c0, float& c1, float& c2, float& c3,
                                         uint32_t a0, uint32_t a1, uint32_t a2, uint32_t a3,
                                         uint32_t b0, uint32_t b1) {
    asm volatile(
        "mma.sync.aligned.m16n8k16.row.col.f32.bf16.bf16.f32 "
        "{%0,%1,%2,%3}, {%4,%5,%6,%7}, {%8,%9}, {%0,%1,%2,%3};"
        : "+f"(c0), "+f"(c1), "+f"(c2), "+f"(c3)
        : "r"(a0), "r"(a1), "r"(a2), "r"(a3), "r"(b0), "r"(b1));
}

// =================================================================
// split-bf16 conversion: in [rows, K0] fp32 -> out [rows, 3*K0] bf16
//   A-side: loBlock=2  -> [hi | hi | lo]
//   B-side: loBlock=1  -> [hi | lo | hi]
// =================================================================
__global__ void split3(const float* __restrict__ in, __nv_bfloat16* __restrict__ out,
                       int rows, int loBlock)
{
    int idx = blockIdx.x * blockDim.x + threadIdx.x;
    int perRow = K0_ / 4;
    int total = rows * perRow;
    if (idx >= total) return;
    int r = idx / perRow;
    int k4 = (idx - r * perRow) * 4;
    float4 v = *reinterpret_cast<const float4*>(in + (size_t)r * K0_ + k4);
    float vv[4] = {v.x, v.y, v.z, v.w};
    __nv_bfloat16 hi[4], lo[4];
#pragma unroll
    for (int i = 0; i < 4; i++) {
        hi[i] = __float2bfloat16(vv[i]);
        lo[i] = __float2bfloat16(vv[i] - __bfloat162float(hi[i]));
    }
    __nv_bfloat16* o = out + (size_t)r * KP_;
    __nv_bfloat162 hp0 = __nv_bfloat162(hi[0], hi[1]);
    __nv_bfloat162 hp1 = __nv_bfloat162(hi[2], hi[3]);
    __nv_bfloat162 lp0 = __nv_bfloat162(lo[0], lo[1]);
    __nv_bfloat162 lp1 = __nv_bfloat162(lo[2], lo[3]);
#pragma unroll
    for (int b = 0; b < 3; b++) {
        __nv_bfloat162* dst = reinterpret_cast<__nv_bfloat162*>(o + b * K0_ + k4);
        if (b == loBlock) { dst[0] = lp0; dst[1] = lp1; }
        else              { dst[0] = hp0; dst[1] = hp1; }
    }
}

__global__ void concat_bias(const float* __restrict__ bq, const float* __restrict__ bk,
                            const float* __restrict__ bv, float* __restrict__ o)
{
    int i = blockIdx.x * blockDim.x + threadIdx.x;
    if (i >= NQKV) return;
    float v;
    if (i < HQ_ * HD_)                 v = bq[i];
    else if (i < HQ_ * HD_ + HKV_ * HD_) v = bk[i - HQ_ * HD_];
    else                               v = bv[i - HQ_ * HD_ - HKV_ * HD_];
    o[i] = v;
}

// =================================================================
// HMMA bf16 GEMM:  C[M,N] = A3[M,KP] * W3[N,KP]^T (+bias), fp32 out
// CTA tile 128x128x32, 128 threads (4 warps), warp grid 2x2,
// warp tile 64x64 (mi=4, ni=8). 4-stage cp.async pipeline.
// =================================================================
constexpr int BKt    = 32;               // bf16 k per stage
constexpr int ASTR   = 40;               // row stride in bf16 (80B; conflict-floor layout)
constexpr int TILE_B = 128 * ASTR * 2;   // bytes per matrix per stage = 10240
constexpr int STAGES = 4;
constexpr int GEMM_SMEM = 2 * STAGES * TILE_B;   // 81920 B

__global__ __launch_bounds__(128, 2)
void gemm_hmma(const __nv_bfloat16* __restrict__ A, const __nv_bfloat16* __restrict__ W,
               const float* __restrict__ bias, float* __restrict__ C, int N)
{
    extern __shared__ char smem[];
    const uint32_t sbase = smem_u32(smem);

    const int tid  = threadIdx.x;
    const int wid  = tid >> 5;
    const int lane = tid & 31;
    const int wm   = wid & 1;            // m: 0..1
    const int wn   = wid >> 1;           // n: 0..1

    const int nb = blockIdx.x, mb = blockIdx.y;
    const __nv_bfloat16* Abase = A + (size_t)mb * 128 * KP_;
    const __nv_bfloat16* Wbase = W + (size_t)nb * 128 * KP_;

    // load slots: 4 per thread per matrix; lin = tid + i*128 -> row = lin>>2, seg = lin&3
    auto load_stage = [&](int c, int st) {
        const uint32_t ad = sbase + (uint32_t)(st * TILE_B);
        const uint32_t wd = sbase + (uint32_t)((STAGES + st) * TILE_B);
        const char* Ak = reinterpret_cast<const char*>(Abase + (size_t)c * BKt);
        const char* Wk = reinterpret_cast<const char*>(Wbase + (size_t)c * BKt);
#pragma unroll
        for (int i = 0; i < 4; i++) {
            int lin = tid + i * 128;
            int r = lin >> 2, sg = lin & 3;
            uint32_t so = (uint32_t)(r * ASTR * 2 + sg * 16);
            cp_async16(ad + so, Ak + (size_t)r * KP_ * 2 + sg * 16);
            cp_async16(wd + so, Wk + (size_t)r * KP_ * 2 + sg * 16);
        }
    };

    // ldmatrix lane offsets (proven R4 mappings)
    // A x4 (per mi): rows wm*64 + mi*16 + (lane&15), col half (lane>>4)*8
    const uint32_t aoffs = (uint32_t)(((wm * 64 + (lane & 15)) * ASTR + (lane >> 4) * 8) * 2);
    // B x4 (per p): rows wn*64 + ((g>>1)*8) + (lane&7), col (g&1)*8,  g = lane>>3
    const int g = lane >> 3;
    const uint32_t boffs = (uint32_t)(((wn * 64 + ((g >> 1) * 8) + (lane & 7)) * ASTR + (g & 1) * 8) * 2);

    float acc[4][8][4];
#pragma unroll
    for (int mi = 0; mi < 4; mi++)
#pragma unroll
        for (int ni = 0; ni < 8; ni++)
#pragma unroll
            for (int q = 0; q < 4; q++) acc[mi][ni][q] = 0.f;

    const int NT = KP_ / BKt;            // 384
    load_stage(0, 0); cp_commit();
    load_stage(1, 1); cp_commit();
    load_stage(2, 2); cp_commit();

    auto compute_stage = [&](int st) {
        const uint32_t ab = sbase + (uint32_t)(st * TILE_B);
        const uint32_t wb = sbase + (uint32_t)((STAGES + st) * TILE_B);
#pragma unroll
        for (int ks = 0; ks < 2; ks++) {
            const uint32_t kshift = (uint32_t)(ks * 16 * 2);
            uint32_t a[4][4];
#pragma unroll
            for (int mi = 0; mi < 4; mi++)
                ldmatrix_x4(a[mi][0], a[mi][1], a[mi][2], a[mi][3],
                            ab + aoffs + (uint32_t)(mi * 16 * ASTR * 2) + kshift);
            uint32_t bfr[8][2];
#pragma unroll
            for (int p = 0; p < 4; p++) {
                uint32_t t0, t1, t2, t3;
                ldmatrix_x4(t0, t1, t2, t3,
                            wb + boffs + (uint32_t)(p * 16 * ASTR * 2) + kshift);
                bfr[2 * p + 0][0] = t0; bfr[2 * p + 0][1] = t1;
                bfr[2 * p + 1][0] = t2; bfr[2 * p + 1][1] = t3;
            }
#pragma unroll
            for (int mi = 0; mi < 4; mi++)
#pragma unroll
                for (int ni = 0; ni < 8; ni++)
                    mma_bf16(acc[mi][ni][0], acc[mi][ni][1], acc[mi][ni][2], acc[mi][ni][3],
                             a[mi][0], a[mi][1], a[mi][2], a[mi][3],
                             bfr[ni][0], bfr[ni][1]);
        }
    };

    for (int c = 0; c < NT; c++) {
        if (c < NT - 2)      cp_wait<2>();
        else if (c == NT - 2) cp_wait<1>();
        else                  cp_wait<0>();
        __syncthreads();
        if (c + 3 < NT) { load_stage(c + 3, (c + 3) & 3); cp_commit(); }
        compute_stage(c & 3);
    }

    // epilogue
    const int mrow0 = mb * 128 + wm * 64 + (lane >> 2);
    const int ncol0 = nb * 128 + wn * 64 + (lane & 3) * 2;
#pragma unroll
    for (int mi = 0; mi < 4; mi++) {
#pragma unroll
        for (int ni = 0; ni < 8; ni++) {
            int row = mrow0 + mi * 16;
            int col = ncol0 + ni * 8;
            float b0 = 0.f, b1 = 0.f;
            if (bias) { b0 = bias[col]; b1 = bias[col + 1]; }
            float2 v0 = {acc[mi][ni][0] + b0, acc[mi][ni][1] + b1};
            float2 v1 = {acc[mi][ni][2] + b0, acc[mi][ni][3] + b1};
            *reinterpret_cast<float2*>(C + (size_t)row * N + col) = v0;
            *reinterpret_cast<float2*>(C + (size_t)(row + 8) * N + col) = v1;
        }
    }
}

// =================================================================
// RoPE + transpose scatter from fused QKV buffer
//   in  : [B*S, NQKV], columns colBase + h*HD + d
//   out : [B, H, S, HD]
// =================================================================
__global__ void rope_scatter(const float* __restrict__ in,
                             const float* __restrict__ cosp,
                             const float* __restrict__ sinp,
                             float* __restrict__ out,
                             int H, int colBase, int doRope)
{
    int idx = blockIdx.x * blockDim.x + threadIdx.x;
    int total = B_ * S_ * H * (HD_ / 2);
    if (idx >= total) return;
    int d = idx & 63;
    int h = (idx >> 6) % H;
    int s = (idx / (64 * H)) % S_;
    int b = idx / (64 * H * S_);

    const float* row = in + (size_t)(b * S_ + s) * NQKV + colBase + (size_t)h * HD_;
    float x0 = row[d], x1 = row[d + 64];
    float o0, o1;
    if (doRope) {
        float c0 = cosp[s * HD_ + d];
        float c1 = cosp[s * HD_ + d + 64];
        float s0 = sinp[s * HD_ + d];
        float s1 = sinp[s * HD_ + d + 64];
        o0 = x0 * c0 - x1 * s0;
        o1 = x1 * c1 + x0 * s1;
    } else {
        o0 = x0; o1 = x1;
    }
    float* orow = out + ((size_t)(b * H + h) * S_ + s) * HD_;
    orow[d] = o0;
    orow[d + 64] = o1;
}

// =================================================================
// Flash attention (fp32, proven correct — next round's HMMA target)
// =================================================================
constexpr int QT = 64, KT = 64;
constexpr int QP = 68;
constexpr int VP = 132;
constexpr int SP = 65;
constexpr int FLASH_SMEM_FLOATS = HD_ * QP * 2 + KT * VP + QT * SP + 3 * QT;
constexpr int FLASH_SMEM_BYTES  = FLASH_SMEM_FLOATS * 4;

__global__ __launch_bounds__(256, 1)
void flash_attn(const float* __restrict__ Q, const float* __restrict__ Kc,
                const float* __restrict__ Vc, float* __restrict__ Oout)
{
    extern __shared__ float sm[];
    float* Qst  = sm;
    float* Kst  = Qst + HD_ * QP;
    float* Vs   = Kst + HD_ * QP;
    float* Ps   = Vs + KT * VP;
    float* mrow = Ps + QT * SP;
    float* lrow = mrow + QT;
    float* frow = lrow + QT;

    const int qt = blockIdx.x;
    const int h  = blockIdx.y;
    const int b  = blockIdx.z;
    const int hk = h >> 2;
    const int tid = threadIdx.x;
    const int tr  = tid >> 4;
    const int tc  = tid & 15;

    const float* Qbase = Q + ((size_t)(b * HQ_ + h) * S_ + (size_t)qt * QT) * HD_;
    const float* Kbase = Kc + (size_t)(b * HKV_ + hk) * S_ * HD_;
    const float* Vbase = Vc + (size_t)(b * HKV_ + hk) * S_ * HD_;

    const int lr = tid & 63;
    const int lg = tid >> 6;
#pragma unroll
    for (int it = 0; it < 8; it++) {
        int dd = (lg + it * 4) * 4;
        float4 v = *reinterpret_cast<const float4*>(Qbase + (size_t)lr * HD_ + dd);
        Qst[(dd + 0) * QP + lr] = v.x;
        Qst[(dd + 1) * QP + lr] = v.y;
        Qst[(dd + 2) * QP + lr] = v.z;
        Qst[(dd + 3) * QP + lr] = v.w;
    }
    if (tid < QT) { mrow[tid] = -1e30f; lrow[tid] = 0.f; }

    float acc[4][8];
#pragma unroll
    for (int i = 0; i < 4; i++)
#pragma unroll
        for (int j = 0; j < 8; j++) acc[i][j] = 0.f;
    __syncthreads();

    const float scale = 0.08838834764831845f;
    const int ntiles = qt + 1;

    for (int j = 0; j < ntiles; j++) {
        const float* Kt = Kbase + (size_t)j * KT * HD_;
        const float* Vt = Vbase + (size_t)j * KT * HD_;
#pragma unroll
        for (int it = 0; it < 8; it++) {
            int dd = (lg + it * 4) * 4;
            float4 v = *reinterpret_cast<const float4*>(Kt + (size_t)lr * HD_ + dd);
            Kst[(dd + 0) * QP + lr] = v.x;
            Kst[(dd + 1) * QP + lr] = v.y;
            Kst[(dd + 2) * QP + lr] = v.z;
            Kst[(dd + 3) * QP + lr] = v.w;
        }
#pragma unroll
        for (int it = 0; it < 8; it++) {
            int lin = tid + it * 256;
            int r = lin >> 5;
            int dd = (lin & 31) * 4;
            float4 v = *reinterpret_cast<const float4*>(Vt + (size_t)r * HD_ + dd);
            *reinterpret_cast<float4*>(Vs + r * VP + dd) = v;
        }
        __syncthreads();

        float sc[4][4];
#pragma unroll
        for (int i = 0; i < 4; i++)
#pragma unroll
            for (int c = 0; c < 4; c++) sc[i][c] = 0.f;

#pragma unroll 4
        for (int d = 0; d < HD_; d++) {
            float4 a4 = *reinterpret_cast<const float4*>(Qst + d * QP + tr * 4);
            float4 b4 = *reinterpret_cast<const float4*>(Kst + d * QP + tc * 4);
            float ra[4] = {a4.x, a4.y, a4.z, a4.w};
            float rb[4] = {b4.x, b4.y, b4.z, b4.w};
#pragma unroll
            for (int i = 0; i < 4; i++)
#pragma unroll
                for (int c = 0; c < 4; c++)
                    sc[i][c] = fmaf(ra[i], rb[c], sc[i][c]);
        }

        const int qglob = qt * QT;
#pragma unroll
        for (int i = 0; i < 4; i++) {
            int r = tr * 4 + i;
#pragma unroll
            for (int c4 = 0; c4 < 4; c4++) {
                int c = tc * 4 + c4;
                float sv = sc[i][c4] * scale;
                if (j * KT + c > qglob + r) sv -= 1e9f;
                Ps[r * SP + c] = sv;
            }
        }
        __syncthreads();

        {
            int warp = tid >> 5, lane = tid & 31;
#pragma unroll
            for (int rr = 0; rr < 8; rr++) {
                int r = warp * 8 + rr;
                float v0 = Ps[r * SP + lane];
                float v1 = Ps[r * SP + lane + 32];
                float mx = fmaxf(v0, v1);
#pragma unroll
                for (int o = 16; o; o >>= 1)
                    mx = fmaxf(mx, __shfl_xor_sync(0xffffffffu, mx, o));
                float mold = mrow[r];
                float mnew = fmaxf(mold, mx);
                float p0 = __expf(v0 - mnew);
                float p1 = __expf(v1 - mnew);
                Ps[r * SP + lane] = p0;
                Ps[r * SP + lane + 32] = p1;
                float psum = p0 + p1;
#pragma unroll
                for (int o = 16; o; o >>= 1)
                    psum += __shfl_xor_sync(0xffffffffu, psum, o);
                if (lane == 0) {
                    float f = __expf(mold - mnew);
                    frow[r] = f;
                    lrow[r] = lrow[r] * f + psum;
                    mrow[r] = mnew;
                }
            }
        }
        __syncthreads();

        float f[4];
#pragma unroll
        for (int i = 0; i < 4; i++) f[i] = frow[tr * 4 + i];
#pragma unroll
        for (int i = 0; i < 4; i++)
#pragma unroll
            for (int jj = 0; jj < 8; jj++) acc[i][jj] *= f[i];

#pragma unroll 2
        for (int c = 0; c < KT; c++) {
            float pa[4];
#pragma unroll
            for (int i = 0; i < 4; i++) pa[i] = Ps[(tr * 4 + i) * SP + c];
            float4 v0 = *reinterpret_cast<const float4*>(Vs + c * VP + tc * 8);
            float4 v1 = *reinterpret_cast<const float4*>(Vs + c * VP + tc * 8 + 4);
            float vb[8] = {v0.x, v0.y, v0.z, v0.w, v1.x, v1.y, v1.z, v1.w};
#pragma unroll
            for (int i = 0; i < 4; i++)
#pragma unroll
                for (int jj = 0; jj < 8; jj++)
                    acc[i][jj] = fmaf(pa[i], vb[jj], acc[i][jj]);
        }
        __syncthreads();
    }

    float inv[4];
#pragma unroll
    for (int i = 0; i < 4; i++) inv[i] = 1.0f / lrow[tr * 4 + i];
#pragma unroll
    for (int i = 0; i < 4; i++) {
        int srow = qt * QT + tr * 4 + i;
        float* orow = Oout + ((size_t)(b * S_ + srow)) * (HQ_ * HD_) + (size_t)h * HD_ + tc * 8;
        float4 o0, o1;
        o0.x = acc[i][0] * inv[i]; o0.y = acc[i][1] * inv[i];
        o0.z = acc[i][2] * inv[i]; o0.w = acc[i][3] * inv[i];
        o1.x = acc[i][4] * inv[i]; o1.y = acc[i][5] * inv[i];
        o1.z = acc[i][6] * inv[i]; o1.w = acc[i][7] * inv[i];
        *reinterpret_cast<float4*>(orow) = o0;
        *reinterpret_cast<float4*>(orow + 4) = o1;
    }
}

// =================================================================
// launch
// =================================================================
extern "C" void kernel_launch(void* const* d_in, const int* in_sizes, int n_in,
                              void* d_out, int out_size)
{
    const float* x    = (const float*)d_in[0];
    const float* cosp = (const float*)d_in[1];
    const float* sinp = (const float*)d_in[2];
    const float* Wq   = (const float*)d_in[3];
    const float* bq   = (const float*)d_in[4];
    const float* Wk   = (const float*)d_in[5];
    const float* bk   = (const float*)d_in[6];
    const float* Wv   = (const float*)d_in[7];
    const float* bv   = (const float*)d_in[8];
    const float* Wo   = (const float*)d_in[9];
    float* out = (float*)d_out;

    float *qkv_raw, *qt, *kt, *vt, *attn, *bqkv;
    __nv_bfloat16 *x3, *wqkv3, *wo3, *attn3;
    cudaGetSymbolAddress((void**)&qkv_raw, g_qkv_raw);
    cudaGetSymbolAddress((void**)&qt,    g_qt);
    cudaGetSymbolAddress((void**)&kt,    g_kt);
    cudaGetSymbolAddress((void**)&vt,    g_vt);
    cudaGetSymbolAddress((void**)&attn,  g_attn);
    cudaGetSymbolAddress((void**)&bqkv,  g_bqkv);
    cudaGetSymbolAddress((void**)&x3,    g_x3);
    cudaGetSymbolAddress((void**)&wqkv3, g_wqkv3);
    cudaGetSymbolAddress((void**)&wo3,   g_wo3);
    cudaGetSymbolAddress((void**)&attn3, g_attn3);

    cudaFuncSetAttribute(flash_attn, cudaFuncAttributeMaxDynamicSharedMemorySize,
                         FLASH_SMEM_BYTES);
    cudaFuncSetAttribute(gemm_hmma, cudaFuncAttributeMaxDynamicSharedMemorySize,
                         GEMM_SMEM);

    // split fp32 -> (hi|hi|lo) / (hi|lo|hi) bf16 operands
    auto splits = [&](const float* src, __nv_bfloat16* dst, int rows, int loB) {
        int total = rows * (K0_ / 4);
        split3<<<(total + 255) / 256, 256>>>(src, dst, rows, loB);
    };
    splits(x,  x3, M_, 2);
    // weights concatenated into one [NQKV, KP] operand
    splits(Wq, wqkv3,                                   HQ_ * HD_,  1);
    splits(Wk, wqkv3 + (size_t)(HQ_ * HD_) * KP_,       HKV_ * HD_, 1);
    splits(Wv, wqkv3 + (size_t)(HQ_ * HD_ + HKV_ * HD_) * KP_, HKV_ * HD_, 1);
    splits(Wo, wo3, DIM_, 1);
    concat_bias<<<(NQKV + 255) / 256, 256>>>(bq, bk, bv, bqkv);

    // fused QKV projection on HMMA tensor cores
    gemm_hmma<<<dim3(NQKV / 128, M_ / 128), 128, GEMM_SMEM>>>(x3, wqkv3, bqkv, qkv_raw, NQKV);

    // RoPE + transpose to (b,h,s,d)
    {
        int npq = B_ * S_ * HQ_ * (HD_ / 2);
        rope_scatter<<<(npq + 255) / 256, 256>>>(qkv_raw, cosp, sinp, qt, HQ_, 0, 1);
        int npk = B_ * S_ * HKV_ * (HD_ / 2);
        rope_scatter<<<(npk + 255) / 256, 256>>>(qkv_raw, cosp, sinp, kt, HKV_, HQ_ * HD_, 1);
        rope_scatter<<<(npk + 255) / 256, 256>>>(qkv_raw, cosp, sinp, vt, HKV_,
                                                 HQ_ * HD_ + HKV_ * HD_, 0);
    }

    // causal GQA flash attention -> (b*s, h*HD)
    flash_attn<<<dim3(S_ / QT, HQ_, B_), 256, FLASH_SMEM_BYTES>>>(qt, kt, vt, attn);

    // output projection on HMMA
    splits(attn, attn3, M_, 2);
    gemm_hmma<<<dim3(DIM_ / 128, M_ / 128), 128, GEMM_SMEM>>>(attn3, wo3, nullptr, out, DIM_);
}

// round 7
// speedup vs baseline: 3.1725x; 1.6608x over previous
#include <cuda_runtime.h>
#include <cuda_bf16.h>
#include <cstdint>

// ---------------- problem constants ----------------
constexpr int B_   = 2;
constexpr int S_   = 2048;
constexpr int DIM_ = 4096;
constexpr int HQ_  = 32;
constexpr int HKV_ = 8;
constexpr int HD_  = 128;
constexpr int M_   = B_ * S_;
constexpr int K0_  = 4096;
constexpr int KP_  = 3 * K0_;                       // split-bf16 tripled K
constexpr int NQKV = HQ_ * HD_ + 2 * HKV_ * HD_;    // 6144
constexpr int HD3  = 3 * HD_;                       // 384 (split d for attention)

// ---------------- scratch (device globals) ----------------
__device__ float g_qkv_raw[(size_t)M_ * NQKV];
__device__ float g_attn[(size_t)M_ * (HQ_ * HD_)];
__device__ float g_bqkv[NQKV];

__device__ __nv_bfloat16 g_x3[(size_t)M_ * KP_];
__device__ __nv_bfloat16 g_wqkv3[(size_t)NQKV * KP_];
__device__ __nv_bfloat16 g_wo3[(size_t)DIM_ * KP_];
__device__ __nv_bfloat16 g_attn3[(size_t)M_ * KP_];

// attention operands
__device__ __nv_bfloat16 g_q3[(size_t)B_ * HQ_ * S_ * HD3];    // [b,h,s,384] hi|hi|lo
__device__ __nv_bfloat16 g_k3[(size_t)B_ * HKV_ * S_ * HD3];   // [b,hk,s,384] hi|lo|hi
__device__ __nv_bfloat16 g_vh[(size_t)B_ * HKV_ * HD_ * S_];   // V^T hi: [b,hk,d,s]
__device__ __nv_bfloat16 g_vl[(size_t)B_ * HKV_ * HD_ * S_];   // V^T lo

// =================================================================
// base-ISA tensor helpers
// =================================================================
__device__ __forceinline__ uint32_t smem_u32(const void* p) {
    uint32_t a;
    asm("{ .reg .u64 t; cvta.to.shared.u64 t, %1; cvt.u32.u64 %0, t; }" : "=r"(a) : "l"(p));
    return a;
}
__device__ __forceinline__ void cp_async16(uint32_t dst, const void* src) {
    asm volatile("cp.async.cg.shared.global [%0], [%1], 16;" :: "r"(dst), "l"(src));
}
__device__ __forceinline__ void cp_commit() { asm volatile("cp.async.commit_group;"); }
template <int N>
__device__ __forceinline__ void cp_wait() { asm volatile("cp.async.wait_group %0;" :: "n"(N)); }
__device__ __forceinline__ void ldmatrix_x4(uint32_t& r0, uint32_t& r1,
                                            uint32_t& r2, uint32_t& r3, uint32_t addr) {
    asm volatile("ldmatrix.sync.aligned.m8n8.x4.shared.b16 {%0,%1,%2,%3}, [%4];"
                 : "=r"(r0), "=r"(r1), "=r"(r2), "=r"(r3) : "r"(addr));
}
__device__ __forceinline__ void mma_bf16(float& c0, float& c1, float& c2, float& c3,
                                         uint32_t a0, uint32_t a1, uint32_t a2, uint32_t a3,
                                         uint32_t b0, uint32_t b1) {
    asm volatile(
        "mma.sync.aligned.m16n8k16.row.col.f32.bf16.bf16.f32 "
        "{%0,%1,%2,%3}, {%4,%5,%6,%7}, {%8,%9}, {%0,%1,%2,%3};"
        : "+f"(c0), "+f"(c1), "+f"(c2), "+f"(c3)
        : "r"(a0), "r"(a1), "r"(a2), "r"(a3), "r"(b0), "r"(b1));
}
__device__ __forceinline__ uint32_t pack_bf16(float lo, float hi) {
    uint32_t r;
    asm("cvt.rn.bf16x2.f32 %0, %1, %2;" : "=r"(r) : "f"(hi), "f"(lo));
    return r;
}

// =================================================================
// split-bf16 conversion for GEMM operands
// =================================================================
__global__ void split3(const float* __restrict__ in, __nv_bfloat16* __restrict__ out,
                       int rows, int loBlock)
{
    int idx = blockIdx.x * blockDim.x + threadIdx.x;
    int perRow = K0_ / 4;
    int total = rows * perRow;
    if (idx >= total) return;
    int r = idx / perRow;
    int k4 = (idx - r * perRow) * 4;
    float4 v = *reinterpret_cast<const float4*>(in + (size_t)r * K0_ + k4);
    float vv[4] = {v.x, v.y, v.z, v.w};
    __nv_bfloat16 hi[4], lo[4];
#pragma unroll
    for (int i = 0; i < 4; i++) {
        hi[i] = __float2bfloat16(vv[i]);
        lo[i] = __float2bfloat16(vv[i] - __bfloat162float(hi[i]));
    }
    __nv_bfloat16* o = out + (size_t)r * KP_;
    __nv_bfloat162 hp0 = __nv_bfloat162(hi[0], hi[1]);
    __nv_bfloat162 hp1 = __nv_bfloat162(hi[2], hi[3]);
    __nv_bfloat162 lp0 = __nv_bfloat162(lo[0], lo[1]);
    __nv_bfloat162 lp1 = __nv_bfloat162(lo[2], lo[3]);
#pragma unroll
    for (int b = 0; b < 3; b++) {
        __nv_bfloat162* dst = reinterpret_cast<__nv_bfloat162*>(o + b * K0_ + k4);
        if (b == loBlock) { dst[0] = lp0; dst[1] = lp1; }
        else              { dst[0] = hp0; dst[1] = hp1; }
    }
}

__global__ void concat_bias(const float* __restrict__ bq, const float* __restrict__ bk,
                            const float* __restrict__ bv, float* __restrict__ o)
{
    int i = blockIdx.x * blockDim.x + threadIdx.x;
    if (i >= NQKV) return;
    float v;
    if (i < HQ_ * HD_)                   v = bq[i];
    else if (i < HQ_ * HD_ + HKV_ * HD_) v = bk[i - HQ_ * HD_];
    else                                 v = bv[i - HQ_ * HD_ - HKV_ * HD_];
    o[i] = v;
}

// =================================================================
// HMMA bf16 GEMM (unchanged, proven)
// =================================================================
constexpr int BKt    = 32;
constexpr int ASTR   = 40;
constexpr int TILE_B = 128 * ASTR * 2;
constexpr int STAGES = 4;
constexpr int GEMM_SMEM = 2 * STAGES * TILE_B;

__global__ __launch_bounds__(128, 2)
void gemm_hmma(const __nv_bfloat16* __restrict__ A, const __nv_bfloat16* __restrict__ W,
               const float* __restrict__ bias, float* __restrict__ C, int N)
{
    extern __shared__ char smem[];
    const uint32_t sbase = smem_u32(smem);

    const int tid  = threadIdx.x;
    const int wid  = tid >> 5;
    const int lane = tid & 31;
    const int wm   = wid & 1;
    const int wn   = wid >> 1;

    const int nb = blockIdx.x, mb = blockIdx.y;
    const __nv_bfloat16* Abase = A + (size_t)mb * 128 * KP_;
    const __nv_bfloat16* Wbase = W + (size_t)nb * 128 * KP_;

    auto load_stage = [&](int c, int st) {
        const uint32_t ad = sbase + (uint32_t)(st * TILE_B);
        const uint32_t wd = sbase + (uint32_t)((STAGES + st) * TILE_B);
        const char* Ak = reinterpret_cast<const char*>(Abase + (size_t)c * BKt);
        const char* Wk = reinterpret_cast<const char*>(Wbase + (size_t)c * BKt);
#pragma unroll
        for (int i = 0; i < 4; i++) {
            int lin = tid + i * 128;
            int r = lin >> 2, sg = lin & 3;
            uint32_t so = (uint32_t)(r * ASTR * 2 + sg * 16);
            cp_async16(ad + so, Ak + (size_t)r * KP_ * 2 + sg * 16);
            cp_async16(wd + so, Wk + (size_t)r * KP_ * 2 + sg * 16);
        }
    };

    const uint32_t aoffs = (uint32_t)(((wm * 64 + (lane & 15)) * ASTR + (lane >> 4) * 8) * 2);
    const int g = lane >> 3;
    const uint32_t boffs = (uint32_t)(((wn * 64 + ((g >> 1) * 8) + (lane & 7)) * ASTR + (g & 1) * 8) * 2);

    float acc[4][8][4];
#pragma unroll
    for (int mi = 0; mi < 4; mi++)
#pragma unroll
        for (int ni = 0; ni < 8; ni++)
#pragma unroll
            for (int q = 0; q < 4; q++) acc[mi][ni][q] = 0.f;

    const int NT = KP_ / BKt;
    load_stage(0, 0); cp_commit();
    load_stage(1, 1); cp_commit();
    load_stage(2, 2); cp_commit();

    auto compute_stage = [&](int st) {
        const uint32_t ab = sbase + (uint32_t)(st * TILE_B);
        const uint32_t wb = sbase + (uint32_t)((STAGES + st) * TILE_B);
#pragma unroll
        for (int ks = 0; ks < 2; ks++) {
            const uint32_t kshift = (uint32_t)(ks * 16 * 2);
            uint32_t a[4][4];
#pragma unroll
            for (int mi = 0; mi < 4; mi++)
                ldmatrix_x4(a[mi][0], a[mi][1], a[mi][2], a[mi][3],
                            ab + aoffs + (uint32_t)(mi * 16 * ASTR * 2) + kshift);
            uint32_t bfr[8][2];
#pragma unroll
            for (int p = 0; p < 4; p++) {
                uint32_t t0, t1, t2, t3;
                ldmatrix_x4(t0, t1, t2, t3,
                            wb + boffs + (uint32_t)(p * 16 * ASTR * 2) + kshift);
                bfr[2 * p + 0][0] = t0; bfr[2 * p + 0][1] = t1;
                bfr[2 * p + 1][0] = t2; bfr[2 * p + 1][1] = t3;
            }
#pragma unroll
            for (int mi = 0; mi < 4; mi++)
#pragma unroll
                for (int ni = 0; ni < 8; ni++)
                    mma_bf16(acc[mi][ni][0], acc[mi][ni][1], acc[mi][ni][2], acc[mi][ni][3],
                             a[mi][0], a[mi][1], a[mi][2], a[mi][3],
                             bfr[ni][0], bfr[ni][1]);
        }
    };

    for (int c = 0; c < NT; c++) {
        if (c < NT - 2)       cp_wait<2>();
        else if (c == NT - 2) cp_wait<1>();
        else                  cp_wait<0>();
        __syncthreads();
        if (c + 3 < NT) { load_stage(c + 3, (c + 3) & 3); cp_commit(); }
        compute_stage(c & 3);
    }

    const int mrow0 = mb * 128 + wm * 64 + (lane >> 2);
    const int ncol0 = nb * 128 + wn * 64 + (lane & 3) * 2;
#pragma unroll
    for (int mi = 0; mi < 4; mi++) {
#pragma unroll
        for (int ni = 0; ni < 8; ni++) {
            int row = mrow0 + mi * 16;
            int col = ncol0 + ni * 8;
            float b0 = 0.f, b1 = 0.f;
            if (bias) { b0 = bias[col]; b1 = bias[col + 1]; }
            float2 v0 = {acc[mi][ni][0] + b0, acc[mi][ni][1] + b1};
            float2 v1 = {acc[mi][ni][2] + b0, acc[mi][ni][3] + b1};
            *reinterpret_cast<float2*>(C + (size_t)row * N + col) = v0;
            *reinterpret_cast<float2*>(C + (size_t)(row + 8) * N + col) = v1;
        }
    }
}

// =================================================================
// RoPE + 3-term split for Q: qkv_raw cols [0,4096) -> q3 [b,h,s,384] hi|hi|lo
// =================================================================
__global__ void rope_q3(const float* __restrict__ in,
                        const float* __restrict__ cosp, const float* __restrict__ sinp,
                        __nv_bfloat16* __restrict__ out)
{
    int idx = blockIdx.x * blockDim.x + threadIdx.x;
    int total = B_ * S_ * HQ_ * 64;
    if (idx >= total) return;
    int d = idx & 63;
    int h = (idx >> 6) % HQ_;
    int s = (idx / (64 * HQ_)) % S_;
    int b = idx / (64 * HQ_ * S_);

    const float* row = in + (size_t)(b * S_ + s) * NQKV + (size_t)h * HD_;
    float x0 = row[d], x1 = row[d + 64];
    float c0 = cosp[s * HD_ + d],  c1 = cosp[s * HD_ + d + 64];
    float s0 = sinp[s * HD_ + d],  s1 = sinp[s * HD_ + d + 64];
    float o0 = x0 * c0 - x1 * s0;
    float o1 = x1 * c1 + x0 * s1;
    __nv_bfloat16 h0 = __float2bfloat16(o0);
    __nv_bfloat16 h1 = __float2bfloat16(o1);
    __nv_bfloat16 l0 = __float2bfloat16(o0 - __bfloat162float(h0));
    __nv_bfloat16 l1 = __float2bfloat16(o1 - __bfloat162float(h1));
    __nv_bfloat16* orow = out + ((size_t)(b * HQ_ + h) * S_ + s) * HD3;
    orow[d] = h0;        orow[d + 64] = h1;         // block0 hi
    orow[128 + d] = h0;  orow[128 + d + 64] = h1;   // block1 hi
    orow[256 + d] = l0;  orow[256 + d + 64] = l1;   // block2 lo
}

// RoPE + split for K: cols [4096,5120) -> k3 [b,hk,s,384] hi|lo|hi
__global__ void rope_k3(const float* __restrict__ in,
                        const float* __restrict__ cosp, const float* __restrict__ sinp,
                        __nv_bfloat16* __restrict__ out)
{
    int idx = blockIdx.x * blockDim.x + threadIdx.x;
    int total = B_ * S_ * HKV_ * 64;
    if (idx >= total) return;
    int d = idx & 63;
    int h = (idx >> 6) % HKV_;
    int s = (idx / (64 * HKV_)) % S_;
    int b = idx / (64 * HKV_ * S_);

    const float* row = in + (size_t)(b * S_ + s) * NQKV + HQ_ * HD_ + (size_t)h * HD_;
    float x0 = row[d], x1 = row[d + 64];
    float c0 = cosp[s * HD_ + d],  c1 = cosp[s * HD_ + d + 64];
    float s0 = sinp[s * HD_ + d],  s1 = sinp[s * HD_ + d + 64];
    float o0 = x0 * c0 - x1 * s0;
    float o1 = x1 * c1 + x0 * s1;
    __nv_bfloat16 h0 = __float2bfloat16(o0);
    __nv_bfloat16 h1 = __float2bfloat16(o1);
    __nv_bfloat16 l0 = __float2bfloat16(o0 - __bfloat162float(h0));
    __nv_bfloat16 l1 = __float2bfloat16(o1 - __bfloat162float(h1));
    __nv_bfloat16* orow = out + ((size_t)(b * HKV_ + h) * S_ + s) * HD3;
    orow[d] = h0;        orow[d + 64] = h1;         // hi
    orow[128 + d] = l0;  orow[128 + d + 64] = l1;   // lo
    orow[256 + d] = h0;  orow[256 + d + 64] = h1;   // hi
}

// V transpose + split: cols [5120,6144) -> vh/vl [b,hk,d,s]
__global__ void v_split_t(const float* __restrict__ in,
                          __nv_bfloat16* __restrict__ vh, __nv_bfloat16* __restrict__ vl)
{
    __shared__ float ts[32][33];
    int s0 = blockIdx.x * 32;
    int d0 = blockIdx.y * 32;
    int bh = blockIdx.z;              // b*HKV + hk
    int tx = threadIdx.x, ty = threadIdx.y;

    const float* src = in + (size_t)((bh >> 3) * S_ + s0) * NQKV
                          + HQ_ * HD_ + HKV_ * HD_ + (bh & 7) * HD_ + d0;
#pragma unroll
    for (int i = 0; i < 4; i++)
        ts[ty + i * 8][tx] = src[(size_t)(ty + i * 8) * NQKV + tx];
    __syncthreads();

    __nv_bfloat16* dh = vh + ((size_t)bh * HD_ + d0) * S_ + s0;
    __nv_bfloat16* dl = vl + ((size_t)bh * HD_ + d0) * S_ + s0;
#pragma unroll
    for (int i = 0; i < 4; i++) {
        int d = ty + i * 8;
        float v = ts[tx][d];
        __nv_bfloat16 hi = __float2bfloat16(v);
        __nv_bfloat16 lo = __float2bfloat16(v - __bfloat162float(hi));
        dh[(size_t)d * S_ + tx] = hi;
        dl[(size_t)d * S_ + tx] = lo;
    }
}

// =================================================================
// HMMA flash attention (causal, GQA).
// 256 thr / 8 warps; Q tile 128 rows (warp m16), KV tile 64 keys.
// Q frags register-resident; double-buffered cp.async K/V tiles.
// QK^T: 3-term split via 384-wide k. PV: p_hi*v_hi + p_hi*v_lo + p_lo*v_hi.
// =================================================================
constexpr int KSTR   = 392;                    // bf16 stride of K rows (784 B, bank+4/row)
constexpr int VSTR   = 72;                     // bf16 stride of V^T rows (144 B)
constexpr int KBYTES = 64 * KSTR * 2;          // 50176
constexpr int VBYTES = 128 * VSTR * 2;         // 18432
constexpr int BUF_B  = KBYTES + 2 * VBYTES;    // 87040
constexpr int FL_SMEM = 2 * BUF_B;             // 174080

__global__ __launch_bounds__(256, 1)
void flash_hmma(const __nv_bfloat16* __restrict__ q3, const __nv_bfloat16* __restrict__ k3,
                const __nv_bfloat16* __restrict__ vth, const __nv_bfloat16* __restrict__ vtl,
                float* __restrict__ Oout)
{
    extern __shared__ char smem[];
    const uint32_t sb = smem_u32(smem);

    const int tid  = threadIdx.x;
    const int wid  = tid >> 5;
    const int lane = tid & 31;
    const int qt = blockIdx.x, h = blockIdx.y, b = blockIdx.z;
    const int hk = h >> 2;

    const __nv_bfloat16* Qb  = q3 + ((size_t)(b * HQ_ + h) * S_ + (size_t)qt * 128) * HD3;
    const __nv_bfloat16* Kb  = k3 + (size_t)(b * HKV_ + hk) * S_ * HD3;
    const __nv_bfloat16* VHb = vth + (size_t)(b * HKV_ + hk) * HD_ * S_;
    const __nv_bfloat16* VLb = vtl + (size_t)(b * HKV_ + hk) * HD_ * S_;

    // ---- stage Q (128x384) into the two K-buffer regions, grab A-frags ----
#pragma unroll
    for (int i = 0; i < 24; i++) {
        int lin = tid + i * 256;
        int row = lin / 48, seg = lin % 48;
        uint32_t dst = sb + (uint32_t)((row >> 6) * BUF_B + (row & 63) * (KSTR * 2) + seg * 16);
        cp_async16(dst, Qb + (size_t)row * HD3 + seg * 8);
    }
    cp_commit(); cp_wait<0>();
    __syncthreads();

    uint32_t qa[24][4];
    {
        uint32_t qbase = sb + (uint32_t)((wid >> 2) * BUF_B
                       + ((wid & 3) * 16 + (lane & 15)) * (KSTR * 2) + (lane >> 4) * 16);
#pragma unroll
        for (int ks = 0; ks < 24; ks++)
            ldmatrix_x4(qa[ks][0], qa[ks][1], qa[ks][2], qa[ks][3], qbase + ks * 32);
    }
    __syncthreads();

    float oacc[16][4];
#pragma unroll
    for (int nf = 0; nf < 16; nf++)
#pragma unroll
        for (int q = 0; q < 4; q++) oacc[nf][q] = 0.f;
    float m0 = -1e30f, m1 = -1e30f, l0 = 0.f, l1 = 0.f;

    const int ntiles = 2 * qt + 2;
    const int g = lane >> 3;

    auto loadKV = [&](int j, int bi) {
        const __nv_bfloat16* Ks = Kb + (size_t)(j * 64) * HD3;
        const uint32_t kb = sb + (uint32_t)(bi * BUF_B);
#pragma unroll
        for (int i = 0; i < 12; i++) {
            int lin = tid + i * 256;
            int row = lin / 48, seg = lin % 48;
            cp_async16(kb + (uint32_t)(row * (KSTR * 2) + seg * 16),
                       Ks + (size_t)row * HD3 + seg * 8);
        }
        const int s0 = j * 64;
        const uint32_t vhb = kb + KBYTES;
        const uint32_t vlb = kb + KBYTES + VBYTES;
#pragma unroll
        for (int i = 0; i < 4; i++) {
            int lin = tid + i * 256;
            int row = lin >> 3, seg = lin & 7;
            cp_async16(vhb + (uint32_t)(row * (VSTR * 2) + seg * 16),
                       VHb + (size_t)row * S_ + s0 + seg * 8);
            cp_async16(vlb + (uint32_t)(row * (VSTR * 2) + seg * 16),
                       VLb + (size_t)row * S_ + s0 + seg * 8);
        }
    };

    loadKV(0, 0); cp_commit();

    const float scale = 0.08838834764831845f;
    const uint32_t kboffs = (uint32_t)((((g >> 1) * 8 + (lane & 7)) * KSTR + (g & 1) * 8) * 2);
    const uint32_t vboffs = (uint32_t)((((g >> 1) * 8 + (lane & 7)) * VSTR + (g & 1) * 8) * 2);

    for (int j = 0; j < ntiles; j++) {
        const int bi = j & 1;
        const bool haveNext = (j + 1 < ntiles);
        if (haveNext) { loadKV(j + 1, (j + 1) & 1); cp_commit(); }
        if (haveNext) cp_wait<1>(); else cp_wait<0>();
        __syncthreads();

        // warp-uniform causal skip: all keys of tile > all rows of warp
        if (64 * j <= qt * 128 + wid * 16 + 15) {
            // ---- scores: S = Q K^T over 384 k ----
            float sc[8][4];
#pragma unroll
            for (int nf = 0; nf < 8; nf++)
#pragma unroll
                for (int q = 0; q < 4; q++) sc[nf][q] = 0.f;

            const uint32_t kb = sb + (uint32_t)(bi * BUF_B) + kboffs;
#pragma unroll
            for (int ks = 0; ks < 24; ks++) {
                uint32_t bfr[8][2];
#pragma unroll
                for (int p = 0; p < 4; p++) {
                    uint32_t t0, t1, t2, t3;
                    ldmatrix_x4(t0, t1, t2, t3, kb + (uint32_t)(p * 16 * KSTR * 2) + ks * 32);
                    bfr[2 * p + 0][0] = t0; bfr[2 * p + 0][1] = t1;
                    bfr[2 * p + 1][0] = t2; bfr[2 * p + 1][1] = t3;
                }
#pragma unroll
                for (int nf = 0; nf < 8; nf++)
                    mma_bf16(sc[nf][0], sc[nf][1], sc[nf][2], sc[nf][3],
                             qa[ks][0], qa[ks][1], qa[ks][2], qa[ks][3],
                             bfr[nf][0], bfr[nf][1]);
            }

            // ---- scale + causal mask ----
            const int r0g = qt * 128 + wid * 16 + (lane >> 2);
            const int key0 = j * 64 + (lane & 3) * 2;
            const bool needMask = (j >= 2 * qt);
#pragma unroll
            for (int nf = 0; nf < 8; nf++) {
#pragma unroll
                for (int q = 0; q < 4; q++) {
                    float sv = sc[nf][q] * scale;
                    if (needMask) {
                        int key = key0 + nf * 8 + (q & 1);
                        int row = r0g + ((q >> 1) ? 8 : 0);
                        if (key > row) sv -= 1e9f;
                    }
                    sc[nf][q] = sv;
                }
            }

            // ---- online softmax (rows r0g, r0g+8) ----
            float mx0 = -1e30f, mx1 = -1e30f;
#pragma unroll
            for (int nf = 0; nf < 8; nf++) {
                mx0 = fmaxf(mx0, fmaxf(sc[nf][0], sc[nf][1]));
                mx1 = fmaxf(mx1, fmaxf(sc[nf][2], sc[nf][3]));
            }
#pragma unroll
            for (int o = 1; o < 4; o <<= 1) {
                mx0 = fmaxf(mx0, __shfl_xor_sync(0xffffffffu, mx0, o));
                mx1 = fmaxf(mx1, __shfl_xor_sync(0xffffffffu, mx1, o));
            }
            float mn0 = fmaxf(m0, mx0), mn1 = fmaxf(m1, mx1);
            float sum0 = 0.f, sum1 = 0.f;
#pragma unroll
            for (int nf = 0; nf < 8; nf++) {
                sc[nf][0] = __expf(sc[nf][0] - mn0);
                sc[nf][1] = __expf(sc[nf][1] - mn0);
                sc[nf][2] = __expf(sc[nf][2] - mn1);
                sc[nf][3] = __expf(sc[nf][3] - mn1);
                sum0 += sc[nf][0] + sc[nf][1];
                sum1 += sc[nf][2] + sc[nf][3];
            }
#pragma unroll
            for (int o = 1; o < 4; o <<= 1) {
                sum0 += __shfl_xor_sync(0xffffffffu, sum0, o);
                sum1 += __shfl_xor_sync(0xffffffffu, sum1, o);
            }
            float f0 = __expf(m0 - mn0), f1 = __expf(m1 - mn1);
            l0 = l0 * f0 + sum0; l1 = l1 * f1 + sum1;
            m0 = mn0; m1 = mn1;
#pragma unroll
            for (int nf = 0; nf < 16; nf++) {
                oacc[nf][0] *= f0; oacc[nf][1] *= f0;
                oacc[nf][2] *= f1; oacc[nf][3] *= f1;
            }

            // ---- PV: O += (p_hi + p_lo)(v_hi + v_lo), 3 products ----
            const uint32_t vhb = sb + (uint32_t)(bi * BUF_B) + KBYTES + vboffs;
            const uint32_t vlb = vhb + VBYTES;
#pragma unroll
            for (int ks = 0; ks < 4; ks++) {
                // A-frags from exp'd score frags 2ks, 2ks+1
                float p00 = sc[2 * ks][0],     p01 = sc[2 * ks][1];
                float p10 = sc[2 * ks][2],     p11 = sc[2 * ks][3];
                float p20 = sc[2 * ks + 1][0], p21 = sc[2 * ks + 1][1];
                float p30 = sc[2 * ks + 1][2], p31 = sc[2 * ks + 1][3];
                uint32_t ahi0 = pack_bf16(p00, p01), ahi1 = pack_bf16(p10, p11);
                uint32_t ahi2 = pack_bf16(p20, p21), ahi3 = pack_bf16(p30, p31);
                float q00 = p00 - __bfloat162float(__float2bfloat16(p00));
                float q01 = p01 - __bfloat162float(__float2bfloat16(p01));
                float q10 = p10 - __bfloat162float(__float2bfloat16(p10));
                float q11 = p11 - __bfloat162float(__float2bfloat16(p11));
                float q20 = p20 - __bfloat162float(__float2bfloat16(p20));
                float q21 = p21 - __bfloat162float(__float2bfloat16(p21));
                float q30 = p30 - __bfloat162float(__float2bfloat16(p30));
                float q31 = p31 - __bfloat162float(__float2bfloat16(p31));
                uint32_t alo0 = pack_bf16(q00, q01), alo1 = pack_bf16(q10, q11);
                uint32_t alo2 = pack_bf16(q20, q21), alo3 = pack_bf16(q30, q31);

#pragma unroll
                for (int p = 0; p < 8; p++) {
                    uint32_t t0, t1, t2, t3, u0, u1, u2, u3;
                    ldmatrix_x4(t0, t1, t2, t3, vhb + (uint32_t)(p * 16 * VSTR * 2) + ks * 32);
                    ldmatrix_x4(u0, u1, u2, u3, vlb + (uint32_t)(p * 16 * VSTR * 2) + ks * 32);
                    int n0 = 2 * p, n1 = 2 * p + 1;
                    mma_bf16(oacc[n0][0], oacc[n0][1], oacc[n0][2], oacc[n0][3],
                             ahi0, ahi1, ahi2, ahi3, t0, t1);
                    mma_bf16(oacc[n0][0], oacc[n0][1], oacc[n0][2], oacc[n0][3],
                             ahi0, ahi1, ahi2, ahi3, u0, u1);
                    mma_bf16(oacc[n0][0], oacc[n0][1], oacc[n0][2], oacc[n0][3],
                             alo0, alo1, alo2, alo3, t0, t1);
                    mma_bf16(oacc[n1][0], oacc[n1][1], oacc[n1][2], oacc[n1][3],
                             ahi0, ahi1, ahi2, ahi3, t2, t3);
                    mma_bf16(oacc[n1][0], oacc[n1][1], oacc[n1][2], oacc[n1][3],
                             ahi0, ahi1, ahi2, ahi3, u2, u3);
                    mma_bf16(oacc[n1][0], oacc[n1][1], oacc[n1][2], oacc[n1][3],
                             alo0, alo1, alo2, alo3, t2, t3);
                }
            }
        }
        __syncthreads();
    }

    // ---- epilogue ----
    float inv0 = 1.0f / l0, inv1 = 1.0f / l1;
    const int srow = qt * 128 + wid * 16 + (lane >> 2);
    float* o0p = Oout + (size_t)(b * S_ + srow) * (HQ_ * HD_) + (size_t)h * HD_ + (lane & 3) * 2;
    float* o1p = o0p + (size_t)8 * (HQ_ * HD_);
#pragma unroll
    for (int nf = 0; nf < 16; nf++) {
        float2 v0 = {oacc[nf][0] * inv0, oacc[nf][1] * inv0};
        float2 v1 = {oacc[nf][2] * inv1, oacc[nf][3] * inv1};
        *reinterpret_cast<float2*>(o0p + nf * 8) = v0;
        *reinterpret_cast<float2*>(o1p + nf * 8) = v1;
    }
}

// =================================================================
// launch
// =================================================================
extern "C" void kernel_launch(void* const* d_in, const int* in_sizes, int n_in,
                              void* d_out, int out_size)
{
    const float* x    = (const float*)d_in[0];
    const float* cosp = (const float*)d_in[1];
    const float* sinp = (const float*)d_in[2];
    const float* Wq   = (const float*)d_in[3];
    const float* bq   = (const float*)d_in[4];
    const float* Wk   = (const float*)d_in[5];
    const float* bk   = (const float*)d_in[6];
    const float* Wv   = (const float*)d_in[7];
    const float* bv   = (const float*)d_in[8];
    const float* Wo   = (const float*)d_in[9];
    float* out = (float*)d_out;

    float *qkv_raw, *attn, *bqkv;
    __nv_bfloat16 *x3, *wqkv3, *wo3, *attn3, *q3, *k3, *vh, *vl;
    cudaGetSymbolAddress((void**)&qkv_raw, g_qkv_raw);
    cudaGetSymbolAddress((void**)&attn,  g_attn);
    cudaGetSymbolAddress((void**)&bqkv,  g_bqkv);
    cudaGetSymbolAddress((void**)&x3,    g_x3);
    cudaGetSymbolAddress((void**)&wqkv3, g_wqkv3);
    cudaGetSymbolAddress((void**)&wo3,   g_wo3);
    cudaGetSymbolAddress((void**)&attn3, g_attn3);
    cudaGetSymbolAddress((void**)&q3,    g_q3);
    cudaGetSymbolAddress((void**)&k3,    g_k3);
    cudaGetSymbolAddress((void**)&vh,    g_vh);
    cudaGetSymbolAddress((void**)&vl,    g_vl);

    cudaFuncSetAttribute(gemm_hmma, cudaFuncAttributeMaxDynamicSharedMemorySize, GEMM_SMEM);
    cudaFuncSetAttribute(flash_hmma, cudaFuncAttributeMaxDynamicSharedMemorySize, FL_SMEM);

    auto splits = [&](const float* src, __nv_bfloat16* dst, int rows, int loB) {
        int total = rows * (K0_ / 4);
        split3<<<(total + 255) / 256, 256>>>(src, dst, rows, loB);
    };
    splits(x,  x3, M_, 2);
    splits(Wq, wqkv3,                                          HQ_ * HD_,  1);
    splits(Wk, wqkv3 + (size_t)(HQ_ * HD_) * KP_,              HKV_ * HD_, 1);
    splits(Wv, wqkv3 + (size_t)(HQ_ * HD_ + HKV_ * HD_) * KP_, HKV_ * HD_, 1);
    splits(Wo, wo3, DIM_, 1);
    concat_bias<<<(NQKV + 255) / 256, 256>>>(bq, bk, bv, bqkv);

    // fused QKV projection
    gemm_hmma<<<dim3(NQKV / 128, M_ / 128), 128, GEMM_SMEM>>>(x3, wqkv3, bqkv, qkv_raw, NQKV);

    // RoPE + attention-operand prep
    {
        int nq = B_ * S_ * HQ_ * 64;
        rope_q3<<<(nq + 255) / 256, 256>>>(qkv_raw, cosp, sinp, q3);
        int nk = B_ * S_ * HKV_ * 64;
        rope_k3<<<(nk + 255) / 256, 256>>>(qkv_raw, cosp, sinp, k3);
        dim3 vg(S_ / 32, HD_ / 32, B_ * HKV_);
        v_split_t<<<vg, dim3(32, 8)>>>(qkv_raw, vh, vl);
    }

    // HMMA causal GQA flash attention -> (b*s, h*HD)
    flash_hmma<<<dim3(S_ / 128, HQ_, B_), 256, FL_SMEM>>>(q3, k3, vh, vl, attn);

    // output projection
    splits(attn, attn3, M_, 2);
    gemm_hmma<<<dim3(DIM_ / 128, M_ / 128), 128, GEMM_SMEM>>>(attn3, wo3, nullptr, out, DIM_);
}